// round 1
// baseline (speedup 1.0000x reference)
#include <cuda_runtime.h>
#include <math.h>

#define NN   50000
#define E2n  400000
#define EE   800000
#define IND  512
#define HID  256
#define CC   8
#define EHID 64

// ---------------- scratch (allocation-free: __device__ globals) ----------------
__device__ __align__(16) float g_h[(size_t)NN * HID];        // 51.2 MB
__device__ __align__(16) float g_lp[(size_t)NN * CC];
__device__ __align__(16) float g_lpsrc[(size_t)EE * CC];     // 25.6 MB
__device__ float g_deg[NN];
__device__ float g_logdeg[NN];
__device__ float g_wpre[EE];
__device__ float g_enorm[EE];
__device__ __align__(16) float g_K[(size_t)EE * 64];         // 204.8 MB
__device__ __align__(16) float g_m[(size_t)EE * CC];
__device__ __align__(16) float g_logf[(size_t)EE * CC];
__device__ __align__(16) float g_sumin[(size_t)NN * CC];
__device__ __align__(16) float g_R[64];                      // R * log2(e)
__device__ __align__(16) float2 g_Wab[HID * EHID];           // interleaved edge_w1

// ---------------- small prep kernels ----------------
__global__ void k_zero_deg() {
    int i = blockIdx.x * blockDim.x + threadIdx.x;
    if (i < NN) g_deg[i] = 0.0f;
}
__global__ void k_zero_sumin() {
    int i = blockIdx.x * blockDim.x + threadIdx.x;
    if (i < NN * CC) g_sumin[i] = 0.0f;
}
__global__ void k_prep_R(const float* __restrict__ R_raw, const float* __restrict__ rsl) {
    int i = threadIdx.x;            // 64 threads
    int r = i >> 3, c = i & 7;
    float v = 0.5f * (R_raw[r * 8 + c] + R_raw[c * 8 + r]);
    float s = log1pf(expf(rsl[0])) + 1e-6f;   // softplus
    g_R[i] = s * tanhf(v) * 1.44269504088896f; // pre-scale by log2(e) for exp2f
}
__global__ void k_prep_wab(const float* __restrict__ w1) {
    int i = blockIdx.x * blockDim.x + threadIdx.x;   // HID*EHID = 16384
    if (i < HID * EHID) {
        int k = i >> 6, j = i & 63;
        g_Wab[i] = make_float2(w1[k * 64 + j], w1[(256 + k) * 64 + j]);
    }
}

// ---------------- encoder: h = relu(x @ enc_w1 + b1) ----------------
// block: 256 threads (j = out column), 16 nodes per block
__global__ void __launch_bounds__(256) k_encoder(const float* __restrict__ x,
                                                 const float* __restrict__ w1,
                                                 const float* __restrict__ b1) {
    __shared__ float4 xs[16][16];   // 16 nodes x 64 k-values per tile
    int n0 = blockIdx.x * 16;
    int j  = threadIdx.x;
    float acc[16];
#pragma unroll
    for (int n = 0; n < 16; n++) acc[n] = 0.0f;
    const float4* x4 = (const float4*)x;

    for (int kt = 0; kt < 8; kt++) {
        __syncthreads();
        {
            int n = threadIdx.x >> 4, q = threadIdx.x & 15;
            xs[n][q] = x4[(size_t)(n0 + n) * 128 + kt * 16 + q];
        }
        __syncthreads();
#pragma unroll
        for (int q2 = 0; q2 < 16; q2++) {
            int k = kt * 64 + q2 * 4;
            float wv0 = w1[(k + 0) * 256 + j];
            float wv1 = w1[(k + 1) * 256 + j];
            float wv2 = w1[(k + 2) * 256 + j];
            float wv3 = w1[(k + 3) * 256 + j];
#pragma unroll
            for (int n2 = 0; n2 < 16; n2++) {
                float4 xv = xs[n2][q2];
                acc[n2] += xv.x * wv0 + xv.y * wv1 + xv.z * wv2 + xv.w * wv3;
            }
        }
    }
    float bb = b1[j];
#pragma unroll
    for (int n = 0; n < 16; n++) {
        g_h[(size_t)(n0 + n) * 256 + j] = fmaxf(acc[n] + bb, 0.0f);
    }
}

// ---------------- logits + log_softmax ----------------
__global__ void __launch_bounds__(256) k_logits(const float* __restrict__ w2,
                                                const float* __restrict__ b2) {
    __shared__ float4 w2s[512];     // 256*8 floats
    for (int i = threadIdx.x; i < 512; i += 256) w2s[i] = ((const float4*)w2)[i];
    __syncthreads();
    int n = blockIdx.x * blockDim.x + threadIdx.x;
    if (n >= NN) return;
    float acc[8];
#pragma unroll
    for (int c = 0; c < 8; c++) acc[c] = 0.0f;
    const float4* h4 = (const float4*)g_h + (size_t)n * 64;
#pragma unroll 8
    for (int k4 = 0; k4 < 64; k4++) {
        float4 hv = h4[k4];
        float hvv[4] = {hv.x, hv.y, hv.z, hv.w};
#pragma unroll
        for (int t = 0; t < 4; t++) {
            float hvt = hvv[t];
            float4 a = w2s[(k4 * 4 + t) * 2 + 0];
            float4 b = w2s[(k4 * 4 + t) * 2 + 1];
            acc[0] += hvt * a.x; acc[1] += hvt * a.y;
            acc[2] += hvt * a.z; acc[3] += hvt * a.w;
            acc[4] += hvt * b.x; acc[5] += hvt * b.y;
            acc[6] += hvt * b.z; acc[7] += hvt * b.w;
        }
    }
    float mx = -1e30f;
#pragma unroll
    for (int c = 0; c < 8; c++) { acc[c] += b2[c]; mx = fmaxf(mx, acc[c]); }
    float s = 0.0f;
#pragma unroll
    for (int c = 0; c < 8; c++) s += __expf(acc[c] - mx);
    float lse = mx + __logf(s);
#pragma unroll
    for (int c = 0; c < 8; c++) g_lp[(size_t)n * 8 + c] = acc[c] - lse;
}

// ---------------- degree ----------------
__global__ void k_deg(const int* __restrict__ ei) {
    int e = blockIdx.x * blockDim.x + threadIdx.x;
    if (e < EE) atomicAdd(&g_deg[ei[e]], 1.0f);
}
__global__ void k_logdeg() {
    int i = blockIdx.x * blockDim.x + threadIdx.x;
    if (i < NN) g_logdeg[i] = __logf(g_deg[i] + 1.0f);
}

// ---------------- edge MLP (fused, 16 edges / block) ----------------
__global__ void __launch_bounds__(256) k_edgemlp(const int* __restrict__ ei,
                                                 const float* __restrict__ w1full,
                                                 const float* __restrict__ b1,
                                                 const float* __restrict__ w2,
                                                 const float* __restrict__ b2) {
    __shared__ float2 pd[16][64];   // 8 KB: (hs*hd, |hs-hd|) per (edge,k)
    __shared__ int   se[16], de[16];
    __shared__ float s1[16], s2[16];
    __shared__ float red[4][4][2];
    int e0  = blockIdx.x * 16;
    int tid = threadIdx.x;
    if (tid < 16) {
        int e = e0 + tid;
        int s = ei[e], d = ei[EE + e];
        se[tid] = s; de[tid] = d;
        float a = g_logdeg[s], b = g_logdeg[d];
        s1[tid] = a + b; s2[tid] = fabsf(a - b);
    }
    int j = tid & 63, g = tid >> 6;
    float acc[4] = {0.f, 0.f, 0.f, 0.f};
    float w2j = w2[j];

    for (int kt = 0; kt < 4; kt++) {
        __syncthreads();
        for (int lin = tid; lin < 1024; lin += 256) {
            int e = lin >> 6, k = lin & 63;
            float hs = g_h[(size_t)se[e] * 256 + kt * 64 + k];
            float hd = g_h[(size_t)de[e] * 256 + kt * 64 + k];
            pd[e][k] = make_float2(hs * hd, fabsf(hs - hd));
        }
        __syncthreads();
#pragma unroll 8
        for (int k = 0; k < 64; k++) {
            float2 wab = g_Wab[(kt * 64 + k) * 64 + j];
#pragma unroll
            for (int el = 0; el < 4; el++) {
                float2 pdv = pd[g * 4 + el][k];
                acc[el] += pdv.x * wab.x + pdv.y * wab.y;
            }
        }
    }
    float wj512 = w1full[512 * 64 + j];
    float wj513 = w1full[513 * 64 + j];
    float bj    = b1[j];
    float partial[4];
#pragma unroll
    for (int el = 0; el < 4; el++) {
        int le = g * 4 + el;
        float eh = fmaxf(acc[el] + s1[le] * wj512 + s2[le] * wj513 + bj, 0.0f);
        float v = eh * w2j;
#pragma unroll
        for (int off = 16; off; off >>= 1) v += __shfl_down_sync(0xffffffffu, v, off);
        partial[el] = v;
    }
    int lane = tid & 31, half = (tid >> 5) & 1;
    if (lane == 0) {
#pragma unroll
        for (int el = 0; el < 4; el++) red[g][el][half] = partial[el];
    }
    __syncthreads();
    if (tid < 16) {
        int gg = tid >> 2, el = tid & 3;
        float raw = red[gg][el][0] + red[gg][el][1] + b2[0];
        g_wpre[e0 + gg * 4 + el] = 0.8f / (1.0f + __expf(-raw));
    }
}

// ---------------- K build + message init ----------------
__global__ void __launch_bounds__(256) k_kinit(const int* __restrict__ ei,
                                               const int* __restrict__ rev) {
    int e = blockIdx.x * blockDim.x + threadIdx.x;
    if (e >= EE) return;
    float w = 0.5f * (g_wpre[e] + g_wpre[rev[e]]);
    int s = ei[e], d = ei[EE + e];
    float dc1 = fmaxf(g_deg[s], 1.0f), dc2 = fmaxf(g_deg[d], 1.0f);
    g_enorm[e] = rsqrtf(dc1 * dc2);
    float4* K4 = (float4*)g_K + (size_t)e * 16;
    const float4* R4 = (const float4*)g_R;
#pragma unroll
    for (int q = 0; q < 16; q++) {
        float4 rv = R4[q];
        K4[q] = make_float4(exp2f(w * rv.x), exp2f(w * rv.y),
                            exp2f(w * rv.z), exp2f(w * rv.w));
    }
    float lps[8], mv[8], sum = 0.0f;
#pragma unroll
    for (int c = 0; c < 8; c++) {
        lps[c] = g_lp[(size_t)s * 8 + c];
        mv[c] = __expf(lps[c]);
        sum += mv[c];
    }
    float inv = 1.0f / sum;
#pragma unroll
    for (int c = 0; c < 8; c++) {
        g_lpsrc[(size_t)e * 8 + c] = lps[c];
        g_m[(size_t)e * 8 + c] = mv[c] * inv;
    }
}

// ---------------- BP kernel A: f = m @ K, log_f, scatter sum_in ----------------
__global__ void __launch_bounds__(256) k_bpA(const int* __restrict__ ei) {
    int e = blockIdx.x * blockDim.x + threadIdx.x;
    if (e >= EE) return;
    const float4* m4 = (const float4*)g_m + (size_t)e * 2;
    float4 ma = m4[0], mb = m4[1];
    float mm[8] = {ma.x, ma.y, ma.z, ma.w, mb.x, mb.y, mb.z, mb.w};
    const float4* K4 = (const float4*)g_K + (size_t)e * 16;
    float f[8] = {0.f, 0.f, 0.f, 0.f, 0.f, 0.f, 0.f, 0.f};
#pragma unroll
    for (int c = 0; c < 8; c++) {
        float4 k0 = K4[c * 2], k1 = K4[c * 2 + 1];
        f[0] += mm[c] * k0.x; f[1] += mm[c] * k0.y;
        f[2] += mm[c] * k0.z; f[3] += mm[c] * k0.w;
        f[4] += mm[c] * k1.x; f[5] += mm[c] * k1.y;
        f[6] += mm[c] * k1.z; f[7] += mm[c] * k1.w;
    }
    float en = g_enorm[e];
    float lf[8];
#pragma unroll
    for (int i = 0; i < 8; i++) lf[i] = __logf(fmaxf(f[i], 1e-12f)) * en;
    float4* lf4 = (float4*)g_logf + (size_t)e * 2;
    lf4[0] = make_float4(lf[0], lf[1], lf[2], lf[3]);
    lf4[1] = make_float4(lf[4], lf[5], lf[6], lf[7]);
    int d = ei[EE + e];
    float* si = &g_sumin[(size_t)d * 8];
#pragma unroll
    for (int i = 0; i < 8; i++) atomicAdd(si + i, lf[i]);
}

// ---------------- BP kernel B: message update ----------------
__global__ void __launch_bounds__(256) k_bpB(const int* __restrict__ ei,
                                             const int* __restrict__ rev,
                                             const float* __restrict__ mlogit) {
    int e = blockIdx.x * blockDim.x + threadIdx.x;
    if (e >= EE) return;
    float alpha = 1.5f / (1.0f + __expf(-mlogit[0]));
    int s = ei[e];
    size_t r = (size_t)rev[e];
    const float4* si4 = (const float4*)g_sumin + (size_t)s * 2;
    const float4* lr4 = (const float4*)g_logf + r * 2;
    const float4* lp4 = (const float4*)g_lpsrc + (size_t)e * 2;
    float4 siA = si4[0], siB = si4[1];
    float4 lrA = lr4[0], lrB = lr4[1];
    float4 lpA = lp4[0], lpB = lp4[1];
    float t[8];
    t[0] = lpA.x + alpha * (siA.x - lrA.x); t[1] = lpA.y + alpha * (siA.y - lrA.y);
    t[2] = lpA.z + alpha * (siA.z - lrA.z); t[3] = lpA.w + alpha * (siA.w - lrA.w);
    t[4] = lpB.x + alpha * (siB.x - lrB.x); t[5] = lpB.y + alpha * (siB.y - lrB.y);
    t[6] = lpB.z + alpha * (siB.z - lrB.z); t[7] = lpB.w + alpha * (siB.w - lrB.w);
    float mx = -1e30f;
#pragma unroll
    for (int i = 0; i < 8; i++) mx = fmaxf(mx, t[i]);
    float ex[8], sum = 0.0f;
#pragma unroll
    for (int i = 0; i < 8; i++) { ex[i] = __expf(t[i] - mx); sum += ex[i]; }
    float inv = 1.0f / sum;
    float4* m4 = (float4*)g_m + (size_t)e * 2;
    float4 mA = m4[0], mB = m4[1];
    float mo[8] = {mA.x, mA.y, mA.z, mA.w, mB.x, mB.y, mB.z, mB.w};
    float mn[8], s2 = 0.0f;
#pragma unroll
    for (int i = 0; i < 8; i++) {
        mn[i] = fmaxf(0.8f * mo[i] + 0.2f * ex[i] * inv, 1e-12f);
        s2 += mn[i];
    }
    float inv2 = 1.0f / s2;
    m4[0] = make_float4(mn[0] * inv2, mn[1] * inv2, mn[2] * inv2, mn[3] * inv2);
    m4[1] = make_float4(mn[4] * inv2, mn[5] * inv2, mn[6] * inv2, mn[7] * inv2);
}

// ---------------- final beliefs ----------------
__global__ void k_belief(const float* __restrict__ mlogit, float* __restrict__ out) {
    int n = blockIdx.x * blockDim.x + threadIdx.x;
    if (n >= NN) return;
    float alpha = 1.5f / (1.0f + __expf(-mlogit[0]));
    float t[8], mx = -1e30f;
#pragma unroll
    for (int c = 0; c < 8; c++) {
        t[c] = g_lp[(size_t)n * 8 + c] + alpha * g_sumin[(size_t)n * 8 + c];
        mx = fmaxf(mx, t[c]);
    }
    float sum = 0.0f;
#pragma unroll
    for (int c = 0; c < 8; c++) { t[c] = __expf(t[c] - mx); sum += t[c]; }
    float inv = 1.0f / sum;
#pragma unroll
    for (int c = 0; c < 8; c++) out[(size_t)n * 8 + c] = t[c] * inv;
}

// ---------------- launch ----------------
extern "C" void kernel_launch(void* const* d_in, const int* in_sizes, int n_in,
                              void* d_out, int out_size) {
    const float* x       = (const float*)d_in[0];
    const int*   ei      = (const int*)d_in[1];
    const int*   rev     = (const int*)d_in[2];
    const float* enc_w1  = (const float*)d_in[3];
    const float* enc_b1  = (const float*)d_in[4];
    const float* enc_w2  = (const float*)d_in[5];
    const float* enc_b2  = (const float*)d_in[6];
    const float* edge_w1 = (const float*)d_in[7];
    const float* edge_b1 = (const float*)d_in[8];
    const float* edge_w2 = (const float*)d_in[9];
    const float* edge_b2 = (const float*)d_in[10];
    const float* R_raw   = (const float*)d_in[11];
    const float* rsl     = (const float*)d_in[12];
    const float* mlogit  = (const float*)d_in[13];
    float* out = (float*)d_out;

    k_prep_R<<<1, 64>>>(R_raw, rsl);
    k_prep_wab<<<64, 256>>>(edge_w1);
    k_encoder<<<NN / 16, 256>>>(x, enc_w1, enc_b1);
    k_logits<<<(NN + 255) / 256, 256>>>(enc_w2, enc_b2);
    k_zero_deg<<<(NN + 255) / 256, 256>>>();
    k_deg<<<(EE + 255) / 256, 256>>>(ei);
    k_logdeg<<<(NN + 255) / 256, 256>>>();
    k_edgemlp<<<EE / 16, 256>>>(ei, edge_w1, edge_b1, edge_w2, edge_b2);
    k_kinit<<<(EE + 255) / 256, 256>>>(ei, rev);

    for (int t = 0; t < 10; t++) {
        k_zero_sumin<<<(NN * CC + 255) / 256, 256>>>();
        k_bpA<<<(EE + 255) / 256, 256>>>(ei);
        k_bpB<<<(EE + 255) / 256, 256>>>(ei, rev, mlogit);
    }
    k_zero_sumin<<<(NN * CC + 255) / 256, 256>>>();
    k_bpA<<<(EE + 255) / 256, 256>>>(ei);
    k_belief<<<(NN + 255) / 256, 256>>>(mlogit, out);
}

// round 2
// speedup vs baseline: 1.2361x; 1.2361x over previous
#include <cuda_runtime.h>
#include <math.h>

#define NN   50000
#define EE   800000
#define HID  256
#define CC   8

typedef unsigned long long ull;

// ---------------- scratch ----------------
__device__ __align__(16) float g_h[(size_t)NN * HID];        // 51.2 MB
__device__ __align__(16) float g_lp[(size_t)NN * CC];
__device__ __align__(16) float g_lpsrc[(size_t)EE * CC];     // 25.6 MB
__device__ float g_deg[NN];
__device__ float g_logdeg[NN];
__device__ float g_wpre[EE];
__device__ float g_w[EE];
__device__ float g_enorm[EE];                                // rsqrt(..)*ln2
__device__ __align__(16) float g_m[(size_t)EE * CC];
__device__ __align__(32) float g_logf[2][(size_t)EE * CC];   // 51.2 MB
__device__ __align__(32) float g_sumin[2][(size_t)NN * CC];
__device__ __align__(16) float g_R[64];                      // R * log2(e)
__device__ __align__(16) float2 g_Wab[HID * 64];             // interleaved edge_w1

// ---------------- f32x2 helpers ----------------
__device__ __forceinline__ ull pack2(float x, float y) {
    ull r; asm("mov.b64 %0, {%1,%2};" : "=l"(r) : "f"(x), "f"(y)); return r;
}
__device__ __forceinline__ float2 unpack2(ull v) {
    float2 r; asm("mov.b64 {%0,%1}, %2;" : "=f"(r.x), "=f"(r.y) : "l"(v)); return r;
}
__device__ __forceinline__ void fma2(ull& d, ull a, ull b) {
    asm("fma.rn.f32x2 %0, %1, %2, %3;" : "=l"(d) : "l"(a), "l"(b), "l"(d));
}

// ---------------- small prep ----------------
__global__ void k_zero_deg() {
    int i = blockIdx.x * blockDim.x + threadIdx.x;
    if (i < NN) g_deg[i] = 0.0f;
}
__global__ void k_zero_sumin(int which) {
    int i = blockIdx.x * blockDim.x + threadIdx.x;
    if (i < NN * CC) g_sumin[which][i] = 0.0f;
}
__global__ void k_prep_R(const float* __restrict__ R_raw, const float* __restrict__ rsl) {
    int i = threadIdx.x;
    int r = i >> 3, c = i & 7;
    float v = 0.5f * (R_raw[r * 8 + c] + R_raw[c * 8 + r]);
    float s = log1pf(expf(rsl[0])) + 1e-6f;
    g_R[i] = s * tanhf(v) * 1.44269504088896f;
}
__global__ void k_prep_wab(const float* __restrict__ w1) {
    int i = blockIdx.x * blockDim.x + threadIdx.x;
    if (i < HID * 64) {
        int k = i >> 6, j = i & 63;
        g_Wab[i] = make_float2(w1[k * 64 + j], w1[(256 + k) * 64 + j]);
    }
}

// ---------------- encoder: 32 nodes/block, f32x2 over node pairs ----------------
__global__ void __launch_bounds__(256) k_encoder(const float* __restrict__ x,
                                                 const float* __restrict__ w1,
                                                 const float* __restrict__ b1) {
    __shared__ float2 xs2[64][16];   // [k-in-tile][pair]: .x=node n0+p, .y=node n0+16+p
    int n0 = blockIdx.x * 32;
    int j  = threadIdx.x;
    ull acc[16];
#pragma unroll
    for (int i = 0; i < 16; i++) acc[i] = 0ull;

    int sn = threadIdx.x >> 3, sq = threadIdx.x & 7;
    int gn = min(n0 + sn, NN - 1);
    const float4* xr = (const float4*)(x + (size_t)gn * 512 + sq * 8);
    int pr = sn & 15, hf = sn >> 4;

    for (int kt = 0; kt < 8; kt++) {
        __syncthreads();
        {
            float4 a = xr[kt * 16 + 0];
            float4 b = xr[kt * 16 + 1];
            float vals[8] = {a.x, a.y, a.z, a.w, b.x, b.y, b.z, b.w};
#pragma unroll
            for (int i = 0; i < 8; i++)
                ((float*)&xs2[sq * 8 + i][pr])[hf] = vals[i];
        }
        __syncthreads();
#pragma unroll 4
        for (int k = 0; k < 64; k++) {
            float wv = w1[(kt * 64 + k) * 256 + j];
            ull wp = pack2(wv, wv);
            const longlong2* row = (const longlong2*)xs2[k];
#pragma unroll
            for (int p2 = 0; p2 < 8; p2++) {
                longlong2 xv = row[p2];
                fma2(acc[p2 * 2 + 0], (ull)xv.x, wp);
                fma2(acc[p2 * 2 + 1], (ull)xv.y, wp);
            }
        }
    }
    float bb = b1[j];
#pragma unroll
    for (int i = 0; i < 16; i++) {
        float2 v = unpack2(acc[i]);
        int nlo = n0 + i, nhi = n0 + 16 + i;
        if (nlo < NN) g_h[(size_t)nlo * 256 + j] = fmaxf(v.x + bb, 0.0f);
        if (nhi < NN) g_h[(size_t)nhi * 256 + j] = fmaxf(v.y + bb, 0.0f);
    }
}

// ---------------- logits + log_softmax (4 lanes per node) ----------------
__global__ void __launch_bounds__(256) k_logits(const float* __restrict__ w2,
                                                const float* __restrict__ b2) {
    __shared__ float4 w2s[512];
    for (int i = threadIdx.x; i < 512; i += 256) w2s[i] = ((const float4*)w2)[i];
    __syncthreads();
    int gtid = blockIdx.x * 256 + threadIdx.x;
    int n = gtid >> 2, q = gtid & 3;
    if (n >= NN) return;
    float acc[8];
#pragma unroll
    for (int c = 0; c < 8; c++) acc[c] = 0.0f;
    const float4* h4 = (const float4*)g_h + (size_t)n * 64 + q * 16;
#pragma unroll
    for (int k4 = 0; k4 < 16; k4++) {
        float4 hv = h4[k4];
        float hvv[4] = {hv.x, hv.y, hv.z, hv.w};
#pragma unroll
        for (int t = 0; t < 4; t++) {
            float hvt = hvv[t];
            int kk = (q * 16 + k4) * 4 + t;
            float4 a = w2s[kk * 2 + 0];
            float4 b = w2s[kk * 2 + 1];
            acc[0] += hvt * a.x; acc[1] += hvt * a.y;
            acc[2] += hvt * a.z; acc[3] += hvt * a.w;
            acc[4] += hvt * b.x; acc[5] += hvt * b.y;
            acc[6] += hvt * b.z; acc[7] += hvt * b.w;
        }
    }
#pragma unroll
    for (int c = 0; c < 8; c++) {
        acc[c] += __shfl_xor_sync(0xffffffffu, acc[c], 1);
        acc[c] += __shfl_xor_sync(0xffffffffu, acc[c], 2);
    }
    if (q == 0) {
        float mx = -1e30f;
#pragma unroll
        for (int c = 0; c < 8; c++) { acc[c] += b2[c]; mx = fmaxf(mx, acc[c]); }
        float s = 0.0f;
#pragma unroll
        for (int c = 0; c < 8; c++) s += __expf(acc[c] - mx);
        float lse = mx + __logf(s);
#pragma unroll
        for (int c = 0; c < 8; c++) g_lp[(size_t)n * 8 + c] = acc[c] - lse;
    }
}

// ---------------- degree ----------------
__global__ void k_deg(const int* __restrict__ ei) {
    int e = blockIdx.x * blockDim.x + threadIdx.x;
    if (e < EE) atomicAdd(&g_deg[ei[e]], 1.0f);
}
__global__ void k_logdeg() {
    int i = blockIdx.x * blockDim.x + threadIdx.x;
    if (i < NN) g_logdeg[i] = __logf(g_deg[i] + 1.0f);
}

// ---------------- edge MLP: 64 edges/block, 4e x 4j register tile, f32x2 ----------------
__global__ void __launch_bounds__(256) k_edgemlp(const int* __restrict__ ei,
                                                 const float* __restrict__ w1full,
                                                 const float* __restrict__ b1,
                                                 const float* __restrict__ w2,
                                                 const float* __restrict__ b2) {
    __shared__ float2 pdT[32][66];   // [k][edge], padded (66) for bank spread + 16B align
    __shared__ float2 wabs[32][64];  // [k][j]
    __shared__ int se[64], de[64];
    __shared__ float s1s[64], s2s[64];
    int e0blk = blockIdx.x * 64;
    int tid = threadIdx.x;
    if (tid < 64) {
        int e = e0blk + tid;
        int s = ei[e], d = ei[EE + e];
        se[tid] = s; de[tid] = d;
        float a = g_logdeg[s], b = g_logdeg[d];
        s1s[tid] = a + b; s2s[tid] = fabsf(a - b);
    }
    int jg = tid & 15, eg = tid >> 4;
    int j0 = jg * 4, ee0 = eg * 4;
    ull acc[4][4];
#pragma unroll
    for (int a = 0; a < 4; a++)
#pragma unroll
        for (int b = 0; b < 4; b++) acc[a][b] = 0ull;

    for (int kt = 0; kt < 16; kt++) {
        __syncthreads();
        int kb = kt * 32;
#pragma unroll
        for (int r = 0; r < 8; r++) {
            int lin = tid + r * 256;
            int k = lin >> 6, jj = lin & 63;
            wabs[k][jj] = g_Wab[(kb + k) * 64 + jj];
        }
#pragma unroll
        for (int r = 0; r < 8; r++) {
            int lin = tid + r * 256;
            int e = lin >> 5, k = lin & 31;
            float hs = g_h[(size_t)se[e] * 256 + kb + k];
            float hd = g_h[(size_t)de[e] * 256 + kb + k];
            pdT[k][e] = make_float2(hs * hd, fabsf(hs - hd));
        }
        __syncthreads();
#pragma unroll 2
        for (int k = 0; k < 32; k++) {
            longlong2 pda = *(const longlong2*)&pdT[k][ee0];
            longlong2 pdb = *(const longlong2*)&pdT[k][ee0 + 2];
            longlong2 wva = *(const longlong2*)&wabs[k][j0];
            longlong2 wvb = *(const longlong2*)&wabs[k][j0 + 2];
            ull pe[4] = {(ull)pda.x, (ull)pda.y, (ull)pdb.x, (ull)pdb.y};
            ull wj[4] = {(ull)wva.x, (ull)wva.y, (ull)wvb.x, (ull)wvb.y};
#pragma unroll
            for (int a = 0; a < 4; a++)
#pragma unroll
                for (int b = 0; b < 4; b++) fma2(acc[a][b], pe[a], wj[b]);
        }
    }
    // epilogue: struct terms + bias, relu, * w2, reduce over jg (lane bits 0-3)
    float w512[4], w513[4], b1v[4], w2v[4];
#pragma unroll
    for (int jl = 0; jl < 4; jl++) {
        int j = j0 + jl;
        w512[jl] = w1full[512 * 64 + j];
        w513[jl] = w1full[513 * 64 + j];
        b1v[jl]  = b1[j];
        w2v[jl]  = w2[j];
    }
    float b2v = b2[0];
#pragma unroll
    for (int e4 = 0; e4 < 4; e4++) {
        int le = ee0 + e4;
        float v = 0.0f;
#pragma unroll
        for (int jl = 0; jl < 4; jl++) {
            float2 pv = unpack2(acc[e4][jl]);
            float pre = pv.x + pv.y + s1s[le] * w512[jl] + s2s[le] * w513[jl] + b1v[jl];
            v += fmaxf(pre, 0.0f) * w2v[jl];
        }
        v += __shfl_xor_sync(0xffffffffu, v, 1);
        v += __shfl_xor_sync(0xffffffffu, v, 2);
        v += __shfl_xor_sync(0xffffffffu, v, 4);
        v += __shfl_xor_sync(0xffffffffu, v, 8);
        if (jg == 0) {
            float raw = v + b2v;
            g_wpre[e0blk + le] = 0.8f / (1.0f + __expf(-raw));
        }
    }
}

// ---------------- scatter helper: vector red ----------------
__device__ __forceinline__ void red_add_v4(float* p, float a, float b, float c, float d) {
    ull gp = (ull)__cvta_generic_to_global(p);
    asm volatile("red.global.add.v4.f32 [%0], {%1,%2,%3,%4};"
                 :: "l"(gp), "f"(a), "f"(b), "f"(c), "f"(d) : "memory");
}

// ---------------- init: w, enorm, m0, lpsrc + first A phase ----------------
__global__ void __launch_bounds__(256) k_initA(const int* __restrict__ ei,
                                               const int* __restrict__ rev) {
    __shared__ float Rs[64];
    if (threadIdx.x < 64) Rs[threadIdx.x] = g_R[threadIdx.x];
    __syncthreads();
    int e = blockIdx.x * 256 + threadIdx.x;   // EE % 256 == 0
    float w = 0.5f * (g_wpre[e] + g_wpre[rev[e]]);
    g_w[e] = w;
    int s = ei[e], d = ei[EE + e];
    float en = rsqrtf(fmaxf(g_deg[s], 1.0f) * fmaxf(g_deg[d], 1.0f)) * 0.6931471805599453f;
    g_enorm[e] = en;
    float lps[8], mv[8], sum = 0.0f;
    const float4* lp4 = (const float4*)(g_lp + (size_t)s * 8);
    float4 lA = lp4[0], lB = lp4[1];
    lps[0]=lA.x; lps[1]=lA.y; lps[2]=lA.z; lps[3]=lA.w;
    lps[4]=lB.x; lps[5]=lB.y; lps[6]=lB.z; lps[7]=lB.w;
#pragma unroll
    for (int c = 0; c < 8; c++) { mv[c] = __expf(lps[c]); sum += mv[c]; }
    float inv = 1.0f / sum;
#pragma unroll
    for (int c = 0; c < 8; c++) mv[c] *= inv;
    float4* o4 = (float4*)(g_lpsrc + (size_t)e * 8);
    o4[0] = lA; o4[1] = lB;
    float4* m4 = (float4*)(g_m + (size_t)e * 8);
    m4[0] = make_float4(mv[0], mv[1], mv[2], mv[3]);
    m4[1] = make_float4(mv[4], mv[5], mv[6], mv[7]);
    float f[8] = {0,0,0,0,0,0,0,0};
#pragma unroll
    for (int c = 0; c < 8; c++)
#pragma unroll
        for (int dd = 0; dd < 8; dd++) f[dd] += mv[c] * exp2f(w * Rs[c * 8 + dd]);
    float lf[8];
#pragma unroll
    for (int i = 0; i < 8; i++) lf[i] = __log2f(fmaxf(f[i], 1e-12f)) * en;
    float4* lf4 = (float4*)(g_logf[0] + (size_t)e * 8);
    lf4[0] = make_float4(lf[0], lf[1], lf[2], lf[3]);
    lf4[1] = make_float4(lf[4], lf[5], lf[6], lf[7]);
    float* sp = &g_sumin[0][(size_t)d * 8];
    red_add_v4(sp,     lf[0], lf[1], lf[2], lf[3]);
    red_add_v4(sp + 4, lf[4], lf[5], lf[6], lf[7]);
}

// ---------------- fused BP step: B(t) then A(t+1) ----------------
__global__ void __launch_bounds__(256) k_bpfused(const int* __restrict__ ei,
                                                 const int* __restrict__ rev,
                                                 const float* __restrict__ mlogit,
                                                 int p) {
    __shared__ float Rs[64];
    if (threadIdx.x < 64) Rs[threadIdx.x] = g_R[threadIdx.x];
    __syncthreads();
    int e = blockIdx.x * 256 + threadIdx.x;
    float alpha = 1.5f / (1.0f + __expf(-mlogit[0]));
    int s = ei[e], d = ei[EE + e];
    size_t r = (size_t)rev[e];
    const float4* si4 = (const float4*)(g_sumin[p] + (size_t)s * 8);
    const float4* lr4 = (const float4*)(g_logf[p] + r * 8);
    const float4* lp4 = (const float4*)(g_lpsrc + (size_t)e * 8);
    float4 siA = si4[0], siB = si4[1];
    float4 lrA = lr4[0], lrB = lr4[1];
    float4 lpA = lp4[0], lpB = lp4[1];
    float t[8];
    t[0] = lpA.x + alpha * (siA.x - lrA.x); t[1] = lpA.y + alpha * (siA.y - lrA.y);
    t[2] = lpA.z + alpha * (siA.z - lrA.z); t[3] = lpA.w + alpha * (siA.w - lrA.w);
    t[4] = lpB.x + alpha * (siB.x - lrB.x); t[5] = lpB.y + alpha * (siB.y - lrB.y);
    t[6] = lpB.z + alpha * (siB.z - lrB.z); t[7] = lpB.w + alpha * (siB.w - lrB.w);
    float mx = -1e30f;
#pragma unroll
    for (int i = 0; i < 8; i++) mx = fmaxf(mx, t[i]);
    float ex[8], sum = 0.0f;
#pragma unroll
    for (int i = 0; i < 8; i++) { ex[i] = __expf(t[i] - mx); sum += ex[i]; }
    float inv = 1.0f / sum;
    float4* m4 = (float4*)(g_m + (size_t)e * 8);
    float4 mA = m4[0], mB = m4[1];
    float mo[8] = {mA.x, mA.y, mA.z, mA.w, mB.x, mB.y, mB.z, mB.w};
    float mn[8], s2 = 0.0f;
#pragma unroll
    for (int i = 0; i < 8; i++) {
        mn[i] = fmaxf(0.8f * mo[i] + 0.2f * ex[i] * inv, 1e-12f);
        s2 += mn[i];
    }
    float inv2 = 1.0f / s2;
#pragma unroll
    for (int i = 0; i < 8; i++) mn[i] *= inv2;
    m4[0] = make_float4(mn[0], mn[1], mn[2], mn[3]);
    m4[1] = make_float4(mn[4], mn[5], mn[6], mn[7]);
    // A phase with m_new, K recomputed
    float w = g_w[e], en = g_enorm[e];
    float f[8] = {0,0,0,0,0,0,0,0};
#pragma unroll
    for (int c = 0; c < 8; c++)
#pragma unroll
        for (int dd = 0; dd < 8; dd++) f[dd] += mn[c] * exp2f(w * Rs[c * 8 + dd]);
    float lf[8];
#pragma unroll
    for (int i = 0; i < 8; i++) lf[i] = __log2f(fmaxf(f[i], 1e-12f)) * en;
    float4* lf4 = (float4*)(g_logf[p ^ 1] + (size_t)e * 8);
    lf4[0] = make_float4(lf[0], lf[1], lf[2], lf[3]);
    lf4[1] = make_float4(lf[4], lf[5], lf[6], lf[7]);
    float* sp = &g_sumin[p ^ 1][(size_t)d * 8];
    red_add_v4(sp,     lf[0], lf[1], lf[2], lf[3]);
    red_add_v4(sp + 4, lf[4], lf[5], lf[6], lf[7]);
}

// ---------------- final beliefs ----------------
__global__ void k_belief(const float* __restrict__ mlogit, float* __restrict__ out) {
    int n = blockIdx.x * blockDim.x + threadIdx.x;
    if (n >= NN) return;
    float alpha = 1.5f / (1.0f + __expf(-mlogit[0]));
    float t[8], mx = -1e30f;
#pragma unroll
    for (int c = 0; c < 8; c++) {
        t[c] = g_lp[(size_t)n * 8 + c] + alpha * g_sumin[0][(size_t)n * 8 + c];
        mx = fmaxf(mx, t[c]);
    }
    float sum = 0.0f;
#pragma unroll
    for (int c = 0; c < 8; c++) { t[c] = __expf(t[c] - mx); sum += t[c]; }
    float inv = 1.0f / sum;
#pragma unroll
    for (int c = 0; c < 8; c++) out[(size_t)n * 8 + c] = t[c] * inv;
}

// ---------------- launch ----------------
extern "C" void kernel_launch(void* const* d_in, const int* in_sizes, int n_in,
                              void* d_out, int out_size) {
    const float* x       = (const float*)d_in[0];
    const int*   ei      = (const int*)d_in[1];
    const int*   rev     = (const int*)d_in[2];
    const float* enc_w1  = (const float*)d_in[3];
    const float* enc_b1  = (const float*)d_in[4];
    const float* enc_w2  = (const float*)d_in[5];
    const float* enc_b2  = (const float*)d_in[6];
    const float* edge_w1 = (const float*)d_in[7];
    const float* edge_b1 = (const float*)d_in[8];
    const float* edge_w2 = (const float*)d_in[9];
    const float* edge_b2 = (const float*)d_in[10];
    const float* R_raw   = (const float*)d_in[11];
    const float* rsl     = (const float*)d_in[12];
    const float* mlogit  = (const float*)d_in[13];
    float* out = (float*)d_out;

    k_prep_R<<<1, 64>>>(R_raw, rsl);
    k_prep_wab<<<64, 256>>>(edge_w1);
    k_encoder<<<(NN + 31) / 32, 256>>>(x, enc_w1, enc_b1);
    k_logits<<<(NN * 4 + 255) / 256, 256>>>(enc_w2, enc_b2);
    k_zero_deg<<<(NN + 255) / 256, 256>>>();
    k_deg<<<(EE + 255) / 256, 256>>>(ei);
    k_logdeg<<<(NN + 255) / 256, 256>>>();
    k_edgemlp<<<EE / 64, 256>>>(ei, edge_w1, edge_b1, edge_w2, edge_b2);
    k_zero_sumin<<<(NN * CC + 255) / 256, 256>>>(0);
    k_initA<<<EE / 256, 256>>>(ei, rev);

    for (int t = 0; t < 10; t++) {
        int p = t & 1;
        k_zero_sumin<<<(NN * CC + 255) / 256, 256>>>(p ^ 1);
        k_bpfused<<<EE / 256, 256>>>(ei, rev, mlogit, p);
    }
    k_belief<<<(NN + 255) / 256, 256>>>(mlogit, out);
}

// round 3
// speedup vs baseline: 1.3093x; 1.0592x over previous
#include <cuda_runtime.h>
#include <cuda_fp16.h>
#include <math.h>

#define NN   50000
#define EE   800000
#define HID  256

typedef unsigned long long ull;

// ---------------- scratch ----------------
__device__ __align__(16) __half g_h16[(size_t)NN * 256];     // 25.6 MB
__device__ __align__(16) float g_lp[(size_t)NN * 8];
__device__ float g_deg[NN];
__device__ float g_logdeg[NN];
__device__ float g_wpre[EE];
__device__ float g_w[EE];
__device__ float g_enorm[EE];                                // rsqrt(..)*ln2
__device__ __align__(16) float g_m[(size_t)EE * 8];
__device__ __align__(32) float g_logf[2][(size_t)EE * 8];    // 51.2 MB
__device__ __align__(32) float g_sumin[11][(size_t)NN * 8];  // 17.6 MB, pre-zeroed
__device__ __align__(16) float g_R[64];                      // R * log2(e)
__device__ __align__(16) float2 g_Wab[HID * 64];             // interleaved edge_w1

// ---------------- f32x2 helpers ----------------
__device__ __forceinline__ ull pack2(float x, float y) {
    ull r; asm("mov.b64 %0, {%1,%2};" : "=l"(r) : "f"(x), "f"(y)); return r;
}
__device__ __forceinline__ float2 unpack2(ull v) {
    float2 r; asm("mov.b64 {%0,%1}, %2;" : "=f"(r.x), "=f"(r.y) : "l"(v)); return r;
}
__device__ __forceinline__ void fma2(ull& d, ull a, ull b) {
    asm("fma.rn.f32x2 %0, %1, %2, %3;" : "=l"(d) : "l"(a), "l"(b), "l"(d));
}
__device__ __forceinline__ void red_add_v4(float* p, float a, float b, float c, float d) {
    ull gp = (ull)__cvta_generic_to_global(p);
    asm volatile("red.global.add.v4.f32 [%0], {%1,%2,%3,%4};"
                 :: "l"(gp), "f"(a), "f"(b), "f"(c), "f"(d) : "memory");
}

// ---------------- launch 0: all prep (zero sumin, zero deg, Wab, R) ----------------
__global__ void k_prep_all(const float* __restrict__ R_raw, const float* __restrict__ rsl,
                           const float* __restrict__ w1) {
    int i = blockIdx.x * 256 + threadIdx.x;
    if (i < 11 * NN * 8) ((float*)g_sumin)[i] = 0.0f;
    if (i < NN) g_deg[i] = 0.0f;
    if (i < HID * 64) {
        int k = i >> 6, j = i & 63;
        g_Wab[i] = make_float2(w1[k * 64 + j], w1[(256 + k) * 64 + j]);
    }
    if (i < 64) {
        int r = i >> 3, c = i & 7;
        float v = 0.5f * (R_raw[r * 8 + c] + R_raw[c * 8 + r]);
        float s = log1pf(expf(rsl[0])) + 1e-6f;
        g_R[i] = s * tanhf(v) * 1.44269504088896f;
    }
}

// ---------------- launch 1: degree ----------------
__global__ void k_deg(const int* __restrict__ ei) {
    int e = blockIdx.x * blockDim.x + threadIdx.x;
    if (e < EE) atomicAdd(&g_deg[ei[e]], 1.0f);
}

// ---------------- launch 2: encoder + logdeg + logits/log_softmax fused ----------------
// 32 nodes/block, 256 threads (j = hidden column), f32x2 over node pairs
__global__ void __launch_bounds__(256) k_encoder(const float* __restrict__ x,
                                                 const float* __restrict__ w1,
                                                 const float* __restrict__ b1,
                                                 const float* __restrict__ w2,
                                                 const float* __restrict__ b2) {
    __shared__ float2 xs2[64][16];    // 8 KB
    __shared__ float  hs[32][260];    // 33.3 KB: h for 32 nodes (padded, 16B-divisible rows)
    __shared__ float  w2t[8][260];    // 8.3 KB: transposed enc_w2
    int tid = threadIdx.x;
    // fused logdeg (deg completed in launch 1)
    if (blockIdx.x < (NN + 255) / 256) {
        int n = blockIdx.x * 256 + tid;
        if (n < NN) g_logdeg[n] = __logf(g_deg[n] + 1.0f);
    }
    // stage transposed w2
    for (int i = tid; i < 2048; i += 256) w2t[i & 7][i >> 3] = w2[i];

    int n0 = blockIdx.x * 32;
    int j  = tid;
    ull acc[16];
#pragma unroll
    for (int i = 0; i < 16; i++) acc[i] = 0ull;

    int sn = tid >> 3, sq = tid & 7;
    int gn = min(n0 + sn, NN - 1);
    const float4* xr = (const float4*)(x + (size_t)gn * 512 + sq * 8);
    int pr = sn & 15, hf = sn >> 4;

    for (int kt = 0; kt < 8; kt++) {
        __syncthreads();
        {
            float4 a = xr[kt * 16 + 0];
            float4 b = xr[kt * 16 + 1];
            float vals[8] = {a.x, a.y, a.z, a.w, b.x, b.y, b.z, b.w};
#pragma unroll
            for (int i = 0; i < 8; i++)
                ((float*)&xs2[sq * 8 + i][pr])[hf] = vals[i];
        }
        __syncthreads();
#pragma unroll 4
        for (int k = 0; k < 64; k++) {
            float wv = w1[(kt * 64 + k) * 256 + j];
            ull wp = pack2(wv, wv);
            const longlong2* row = (const longlong2*)xs2[k];
#pragma unroll
            for (int p2 = 0; p2 < 8; p2++) {
                longlong2 xv = row[p2];
                fma2(acc[p2 * 2 + 0], (ull)xv.x, wp);
                fma2(acc[p2 * 2 + 1], (ull)xv.y, wp);
            }
        }
    }
    float bb = b1[j];
#pragma unroll
    for (int i = 0; i < 16; i++) {
        float2 v = unpack2(acc[i]);
        float hlo = fmaxf(v.x + bb, 0.0f);
        float hhi = fmaxf(v.y + bb, 0.0f);
        hs[i][j] = hlo; hs[16 + i][j] = hhi;
        int nlo = n0 + i, nhi = n0 + 16 + i;
        if (nlo < NN) g_h16[(size_t)nlo * 256 + j] = __float2half_rn(hlo);
        if (nhi < NN) g_h16[(size_t)nhi * 256 + j] = __float2half_rn(hhi);
    }
    __syncthreads();
    // logits: node nl = tid>>3 (0..31), class c = tid&7
    int nl = tid >> 3, c = tid & 7;
    float lacc = 0.0f;
    const float4* hrow = (const float4*)hs[nl];
    const float4* wrow = (const float4*)w2t[c];
#pragma unroll 8
    for (int q = 0; q < 64; q++) {
        float4 a = hrow[q], b = wrow[q];
        lacc += a.x * b.x + a.y * b.y + a.z * b.z + a.w * b.w;
    }
    lacc += b2[c];
    float mx = lacc;
    mx = fmaxf(mx, __shfl_xor_sync(0xffffffffu, mx, 1));
    mx = fmaxf(mx, __shfl_xor_sync(0xffffffffu, mx, 2));
    mx = fmaxf(mx, __shfl_xor_sync(0xffffffffu, mx, 4));
    float exv = __expf(lacc - mx);
    float s = exv;
    s += __shfl_xor_sync(0xffffffffu, s, 1);
    s += __shfl_xor_sync(0xffffffffu, s, 2);
    s += __shfl_xor_sync(0xffffffffu, s, 4);
    float lse = mx + __logf(s);
    int n = n0 + nl;
    if (n < NN) g_lp[(size_t)n * 8 + c] = lacc - lse;
}

// ---------------- launch 3 (CAPTURED by ncu): edge MLP, fp16 h ----------------
__global__ void __launch_bounds__(256) k_edgemlp(const int* __restrict__ ei,
                                                 const float* __restrict__ w1full,
                                                 const float* __restrict__ b1,
                                                 const float* __restrict__ w2,
                                                 const float* __restrict__ b2) {
    __shared__ float2 pdT[32][66];
    __shared__ float2 wabs[32][64];
    __shared__ int se[64], de[64];
    __shared__ float s1s[64], s2s[64];
    int e0blk = blockIdx.x * 64;
    int tid = threadIdx.x;
    if (tid < 64) {
        int e = e0blk + tid;
        int s = ei[e], d = ei[EE + e];
        se[tid] = s; de[tid] = d;
        float a = g_logdeg[s], b = g_logdeg[d];
        s1s[tid] = a + b; s2s[tid] = fabsf(a - b);
    }
    int jg = tid & 15, eg = tid >> 4;
    int j0 = jg * 4, ee0 = eg * 4;
    ull acc[4][4];
#pragma unroll
    for (int a = 0; a < 4; a++)
#pragma unroll
        for (int b = 0; b < 4; b++) acc[a][b] = 0ull;

    for (int kt = 0; kt < 16; kt++) {
        __syncthreads();
        int kb = kt * 32;
#pragma unroll
        for (int r = 0; r < 8; r++) {
            int lin = tid + r * 256;
            int k = lin >> 6, jj = lin & 63;
            wabs[k][jj] = g_Wab[(kb + k) * 64 + jj];
        }
#pragma unroll
        for (int r = 0; r < 4; r++) {
            int lin = tid + r * 256;
            int e = lin >> 4, kp = lin & 15;
            const __half2* hp = (const __half2*)(g_h16 + (size_t)se[e] * 256 + kb);
            const __half2* dp = (const __half2*)(g_h16 + (size_t)de[e] * 256 + kb);
            float2 a = __half22float2(hp[kp]);
            float2 b = __half22float2(dp[kp]);
            pdT[kp * 2 + 0][e] = make_float2(a.x * b.x, fabsf(a.x - b.x));
            pdT[kp * 2 + 1][e] = make_float2(a.y * b.y, fabsf(a.y - b.y));
        }
        __syncthreads();
#pragma unroll 2
        for (int k = 0; k < 32; k++) {
            longlong2 pda = *(const longlong2*)&pdT[k][ee0];
            longlong2 pdb = *(const longlong2*)&pdT[k][ee0 + 2];
            longlong2 wva = *(const longlong2*)&wabs[k][j0];
            longlong2 wvb = *(const longlong2*)&wabs[k][j0 + 2];
            ull pe[4] = {(ull)pda.x, (ull)pda.y, (ull)pdb.x, (ull)pdb.y};
            ull wj[4] = {(ull)wva.x, (ull)wva.y, (ull)wvb.x, (ull)wvb.y};
#pragma unroll
            for (int a = 0; a < 4; a++)
#pragma unroll
                for (int b = 0; b < 4; b++) fma2(acc[a][b], pe[a], wj[b]);
        }
    }
    float w512[4], w513[4], b1v[4], w2v[4];
#pragma unroll
    for (int jl = 0; jl < 4; jl++) {
        int j = j0 + jl;
        w512[jl] = w1full[512 * 64 + j];
        w513[jl] = w1full[513 * 64 + j];
        b1v[jl]  = b1[j];
        w2v[jl]  = w2[j];
    }
    float b2v = b2[0];
#pragma unroll
    for (int e4 = 0; e4 < 4; e4++) {
        int le = ee0 + e4;
        float v = 0.0f;
#pragma unroll
        for (int jl = 0; jl < 4; jl++) {
            float2 pv = unpack2(acc[e4][jl]);
            float pre = pv.x + pv.y + s1s[le] * w512[jl] + s2s[le] * w513[jl] + b1v[jl];
            v += fmaxf(pre, 0.0f) * w2v[jl];
        }
        v += __shfl_xor_sync(0xffffffffu, v, 1);
        v += __shfl_xor_sync(0xffffffffu, v, 2);
        v += __shfl_xor_sync(0xffffffffu, v, 4);
        v += __shfl_xor_sync(0xffffffffu, v, 8);
        if (jg == 0) {
            float raw = v + b2v;
            g_wpre[e0blk + le] = 0.8f / (1.0f + __expf(-raw));
        }
    }
}

// ---------------- launch 4: init (w, enorm, m0) + first A phase ----------------
__global__ void __launch_bounds__(256) k_initA(const int* __restrict__ ei,
                                               const int* __restrict__ rev) {
    __shared__ float Rs[64];
    if (threadIdx.x < 64) Rs[threadIdx.x] = g_R[threadIdx.x];
    __syncthreads();
    int e = blockIdx.x * 256 + threadIdx.x;
    float w = 0.5f * (g_wpre[e] + g_wpre[rev[e]]);
    g_w[e] = w;
    int s = ei[e], d = ei[EE + e];
    float en = rsqrtf(fmaxf(g_deg[s], 1.0f) * fmaxf(g_deg[d], 1.0f)) * 0.6931471805599453f;
    g_enorm[e] = en;
    const float4* lp4 = (const float4*)(g_lp + (size_t)s * 8);
    float4 lA = lp4[0], lB = lp4[1];
    float lps[8] = {lA.x, lA.y, lA.z, lA.w, lB.x, lB.y, lB.z, lB.w};
    float mv[8], sum = 0.0f;
#pragma unroll
    for (int c = 0; c < 8; c++) { mv[c] = __expf(lps[c]); sum += mv[c]; }
    float inv = 1.0f / sum;
#pragma unroll
    for (int c = 0; c < 8; c++) mv[c] *= inv;
    float4* m4 = (float4*)(g_m + (size_t)e * 8);
    m4[0] = make_float4(mv[0], mv[1], mv[2], mv[3]);
    m4[1] = make_float4(mv[4], mv[5], mv[6], mv[7]);
    float f[8] = {0,0,0,0,0,0,0,0};
#pragma unroll
    for (int c = 0; c < 8; c++)
#pragma unroll
        for (int dd = 0; dd < 8; dd++) f[dd] += mv[c] * exp2f(w * Rs[c * 8 + dd]);
    float lf[8];
#pragma unroll
    for (int i = 0; i < 8; i++) lf[i] = __log2f(fmaxf(f[i], 1e-12f)) * en;
    float4* lf4 = (float4*)(g_logf[0] + (size_t)e * 8);
    lf4[0] = make_float4(lf[0], lf[1], lf[2], lf[3]);
    lf4[1] = make_float4(lf[4], lf[5], lf[6], lf[7]);
    float* sp = &g_sumin[0][(size_t)d * 8];
    red_add_v4(sp,     lf[0], lf[1], lf[2], lf[3]);
    red_add_v4(sp + 4, lf[4], lf[5], lf[6], lf[7]);
}

// ---------------- BP step t: B(t) then A(t+1); sumin[t] -> sumin[t+1] ----------------
__global__ void __launch_bounds__(256) k_bpfused(const int* __restrict__ ei,
                                                 const int* __restrict__ rev,
                                                 const float* __restrict__ mlogit,
                                                 int t) {
    __shared__ float Rs[64];
    if (threadIdx.x < 64) Rs[threadIdx.x] = g_R[threadIdx.x];
    __syncthreads();
    int e = blockIdx.x * 256 + threadIdx.x;
    int p = t & 1;
    float alpha = 1.5f / (1.0f + __expf(-mlogit[0]));
    int s = ei[e], d = ei[EE + e];
    size_t r = (size_t)rev[e];
    const float4* si4 = (const float4*)(g_sumin[t] + (size_t)s * 8);
    const float4* lr4 = (const float4*)(g_logf[p] + r * 8);
    const float4* lp4 = (const float4*)(g_lp + (size_t)s * 8);
    float4* m4 = (float4*)(g_m + (size_t)e * 8);
    float4 siA = si4[0], siB = si4[1];
    float4 lrA = lr4[0], lrB = lr4[1];
    float4 lpA = lp4[0], lpB = lp4[1];
    float4 mA = m4[0], mB = m4[1];
    float tt[8];
    tt[0] = lpA.x + alpha * (siA.x - lrA.x); tt[1] = lpA.y + alpha * (siA.y - lrA.y);
    tt[2] = lpA.z + alpha * (siA.z - lrA.z); tt[3] = lpA.w + alpha * (siA.w - lrA.w);
    tt[4] = lpB.x + alpha * (siB.x - lrB.x); tt[5] = lpB.y + alpha * (siB.y - lrB.y);
    tt[6] = lpB.z + alpha * (siB.z - lrB.z); tt[7] = lpB.w + alpha * (siB.w - lrB.w);
    float mx = -1e30f;
#pragma unroll
    for (int i = 0; i < 8; i++) mx = fmaxf(mx, tt[i]);
    float ex[8], sum = 0.0f;
#pragma unroll
    for (int i = 0; i < 8; i++) { ex[i] = __expf(tt[i] - mx); sum += ex[i]; }
    float inv = 1.0f / sum;
    float mo[8] = {mA.x, mA.y, mA.z, mA.w, mB.x, mB.y, mB.z, mB.w};
    float mn[8], s2 = 0.0f;
#pragma unroll
    for (int i = 0; i < 8; i++) {
        mn[i] = fmaxf(0.8f * mo[i] + 0.2f * ex[i] * inv, 1e-12f);
        s2 += mn[i];
    }
    float inv2 = 1.0f / s2;
#pragma unroll
    for (int i = 0; i < 8; i++) mn[i] *= inv2;
    m4[0] = make_float4(mn[0], mn[1], mn[2], mn[3]);
    m4[1] = make_float4(mn[4], mn[5], mn[6], mn[7]);
    float w = g_w[e], en = g_enorm[e];
    float f[8] = {0,0,0,0,0,0,0,0};
#pragma unroll
    for (int c = 0; c < 8; c++)
#pragma unroll
        for (int dd = 0; dd < 8; dd++) f[dd] += mn[c] * exp2f(w * Rs[c * 8 + dd]);
    float lf[8];
#pragma unroll
    for (int i = 0; i < 8; i++) lf[i] = __log2f(fmaxf(f[i], 1e-12f)) * en;
    float4* lf4 = (float4*)(g_logf[p ^ 1] + (size_t)e * 8);
    lf4[0] = make_float4(lf[0], lf[1], lf[2], lf[3]);
    lf4[1] = make_float4(lf[4], lf[5], lf[6], lf[7]);
    float* sp = &g_sumin[t + 1][(size_t)d * 8];
    red_add_v4(sp,     lf[0], lf[1], lf[2], lf[3]);
    red_add_v4(sp + 4, lf[4], lf[5], lf[6], lf[7]);
}

// ---------------- final beliefs ----------------
__global__ void k_belief(const float* __restrict__ mlogit, float* __restrict__ out) {
    int n = blockIdx.x * blockDim.x + threadIdx.x;
    if (n >= NN) return;
    float alpha = 1.5f / (1.0f + __expf(-mlogit[0]));
    float t[8], mx = -1e30f;
#pragma unroll
    for (int c = 0; c < 8; c++) {
        t[c] = g_lp[(size_t)n * 8 + c] + alpha * g_sumin[10][(size_t)n * 8 + c];
        mx = fmaxf(mx, t[c]);
    }
    float sum = 0.0f;
#pragma unroll
    for (int c = 0; c < 8; c++) { t[c] = __expf(t[c] - mx); sum += t[c]; }
    float inv = 1.0f / sum;
#pragma unroll
    for (int c = 0; c < 8; c++) out[(size_t)n * 8 + c] = t[c] * inv;
}

// ---------------- launch ----------------
extern "C" void kernel_launch(void* const* d_in, const int* in_sizes, int n_in,
                              void* d_out, int out_size) {
    const float* x       = (const float*)d_in[0];
    const int*   ei      = (const int*)d_in[1];
    const int*   rev     = (const int*)d_in[2];
    const float* enc_w1  = (const float*)d_in[3];
    const float* enc_b1  = (const float*)d_in[4];
    const float* enc_w2  = (const float*)d_in[5];
    const float* enc_b2  = (const float*)d_in[6];
    const float* edge_w1 = (const float*)d_in[7];
    const float* edge_b1 = (const float*)d_in[8];
    const float* edge_w2 = (const float*)d_in[9];
    const float* edge_b2 = (const float*)d_in[10];
    const float* R_raw   = (const float*)d_in[11];
    const float* rsl     = (const float*)d_in[12];
    const float* mlogit  = (const float*)d_in[13];
    float* out = (float*)d_out;

    k_prep_all<<<(11 * NN * 8 + 255) / 256, 256>>>(R_raw, rsl, edge_w1);      // 0
    k_deg<<<(EE + 255) / 256, 256>>>(ei);                                     // 1
    k_encoder<<<(NN + 31) / 32, 256>>>(x, enc_w1, enc_b1, enc_w2, enc_b2);    // 2
    k_edgemlp<<<EE / 64, 256>>>(ei, edge_w1, edge_b1, edge_w2, edge_b2);      // 3 <- profiled
    k_initA<<<EE / 256, 256>>>(ei, rev);                                      // 4
    for (int t = 0; t < 10; t++)
        k_bpfused<<<EE / 256, 256>>>(ei, rev, mlogit, t);                     // 5..14
    k_belief<<<(NN + 255) / 256, 256>>>(mlogit, out);                         // 15
}

// round 4
// speedup vs baseline: 5.4381x; 4.1533x over previous
#include <cuda_runtime.h>
#include <cuda_fp16.h>
#include <math.h>

#define NN   50000
#define EE   800000
#define HID  256

typedef unsigned long long ull;

// ---------------- scratch ----------------
__device__ __align__(16) __half g_h16[(size_t)NN * 256];     // 25.6 MB
__device__ __align__(16) float g_lp[(size_t)NN * 8];
__device__ float g_deg[NN];
__device__ float g_logdeg[NN];
__device__ float g_wpre[EE];
__device__ float g_w[EE];
__device__ float g_enorm[EE];                                // rsqrt(..)*ln2
__device__ __align__(16) float g_m[(size_t)EE * 8];
__device__ __align__(32) float g_logf[2][(size_t)EE * 8];    // 51.2 MB
__device__ __align__(32) float g_sumin[11][(size_t)NN * 8];  // 17.6 MB, pre-zeroed
__device__ __align__(16) float g_R[64];                      // R * log2(e)
__device__ __align__(16) __half g_Wab16[512 * 64];           // interleaved+swizzled edge_w1 (fp16)

// ---------------- f32x2 helpers ----------------
__device__ __forceinline__ ull pack2(float x, float y) {
    ull r; asm("mov.b64 %0, {%1,%2};" : "=l"(r) : "f"(x), "f"(y)); return r;
}
__device__ __forceinline__ float2 unpack2(ull v) {
    float2 r; asm("mov.b64 {%0,%1}, %2;" : "=f"(r.x), "=f"(r.y) : "l"(v)); return r;
}
__device__ __forceinline__ void fma2(ull& d, ull a, ull b) {
    asm("fma.rn.f32x2 %0, %1, %2, %3;" : "=l"(d) : "l"(a), "l"(b), "l"(d));
}
__device__ __forceinline__ void red_add_v4(float* p, float a, float b, float c, float d) {
    ull gp = (ull)__cvta_generic_to_global(p);
    asm volatile("red.global.add.v4.f32 [%0], {%1,%2,%3,%4};"
                 :: "l"(gp), "f"(a), "f"(b), "f"(c), "f"(d) : "memory");
}
__device__ __forceinline__ unsigned smem_u32(const void* p) {
    unsigned a;
    asm("{ .reg .u64 t; cvta.to.shared.u64 t, %1; cvt.u32.u64 %0, t; }" : "=r"(a) : "l"(p));
    return a;
}

// ---------------- launch 0: all prep ----------------
__global__ void k_prep_all(const float* __restrict__ R_raw, const float* __restrict__ rsl,
                           const float* __restrict__ w1) {
    int i = blockIdx.x * 256 + threadIdx.x;
    if (i < 11 * NN * 8) ((float*)g_sumin)[i] = 0.0f;
    if (i < NN) g_deg[i] = 0.0f;
    if (i < 512 * 64) {
        // feature k: k=2i -> w1[i][j] (p), k=2i+1 -> w1[256+i][j] (d)
        // stored with 16B-chunk XOR swizzle for conflict-free ldmatrix
        int k = i >> 6, j = i & 63;
        int c = j >> 3, u = j & 7;
        int pos = (k << 6) + (((c ^ (k & 7)) << 3) + u);
        int hc = k >> 1;
        float v = (k & 1) ? w1[(256 + hc) * 64 + j] : w1[hc * 64 + j];
        g_Wab16[pos] = __float2half_rn(v);
    }
    if (i < 64) {
        int r = i >> 3, c = i & 7;
        float v = 0.5f * (R_raw[r * 8 + c] + R_raw[c * 8 + r]);
        float s = log1pf(expf(rsl[0])) + 1e-6f;
        g_R[i] = s * tanhf(v) * 1.44269504088896f;
    }
}

// ---------------- launch 1: degree ----------------
__global__ void k_deg(const int* __restrict__ ei) {
    int e = blockIdx.x * blockDim.x + threadIdx.x;
    if (e < EE) atomicAdd(&g_deg[ei[e]], 1.0f);
}

// ---------------- launch 2: encoder + logdeg + logits/log_softmax fused ----------------
__global__ void __launch_bounds__(256) k_encoder(const float* __restrict__ x,
                                                 const float* __restrict__ w1,
                                                 const float* __restrict__ b1,
                                                 const float* __restrict__ w2,
                                                 const float* __restrict__ b2) {
    __shared__ float2 xs2[64][16];
    __shared__ float  hs[32][260];
    __shared__ float  w2t[8][260];
    int tid = threadIdx.x;
    if (blockIdx.x < (NN + 255) / 256) {
        int n = blockIdx.x * 256 + tid;
        if (n < NN) g_logdeg[n] = __logf(g_deg[n] + 1.0f);
    }
    for (int i = tid; i < 2048; i += 256) w2t[i & 7][i >> 3] = w2[i];

    int n0 = blockIdx.x * 32;
    int j  = tid;
    ull acc[16];
#pragma unroll
    for (int i = 0; i < 16; i++) acc[i] = 0ull;

    int sn = tid >> 3, sq = tid & 7;
    int gn = min(n0 + sn, NN - 1);
    const float4* xr = (const float4*)(x + (size_t)gn * 512 + sq * 8);
    int pr = sn & 15, hf = sn >> 4;

    for (int kt = 0; kt < 8; kt++) {
        __syncthreads();
        {
            float4 a = xr[kt * 16 + 0];
            float4 b = xr[kt * 16 + 1];
            float vals[8] = {a.x, a.y, a.z, a.w, b.x, b.y, b.z, b.w};
#pragma unroll
            for (int i = 0; i < 8; i++)
                ((float*)&xs2[sq * 8 + i][pr])[hf] = vals[i];
        }
        __syncthreads();
#pragma unroll 4
        for (int k = 0; k < 64; k++) {
            float wv = w1[(kt * 64 + k) * 256 + j];
            ull wp = pack2(wv, wv);
            const longlong2* row = (const longlong2*)xs2[k];
#pragma unroll
            for (int p2 = 0; p2 < 8; p2++) {
                longlong2 xv = row[p2];
                fma2(acc[p2 * 2 + 0], (ull)xv.x, wp);
                fma2(acc[p2 * 2 + 1], (ull)xv.y, wp);
            }
        }
    }
    float bb = b1[j];
#pragma unroll
    for (int i = 0; i < 16; i++) {
        float2 v = unpack2(acc[i]);
        float hlo = fmaxf(v.x + bb, 0.0f);
        float hhi = fmaxf(v.y + bb, 0.0f);
        hs[i][j] = hlo; hs[16 + i][j] = hhi;
        int nlo = n0 + i, nhi = n0 + 16 + i;
        if (nlo < NN) g_h16[(size_t)nlo * 256 + j] = __float2half_rn(hlo);
        if (nhi < NN) g_h16[(size_t)nhi * 256 + j] = __float2half_rn(hhi);
    }
    __syncthreads();
    int nl = tid >> 3, c = tid & 7;
    float lacc = 0.0f;
    const float4* hrow = (const float4*)hs[nl];
    const float4* wrow = (const float4*)w2t[c];
#pragma unroll 8
    for (int q = 0; q < 64; q++) {
        float4 a = hrow[q], b = wrow[q];
        lacc += a.x * b.x + a.y * b.y + a.z * b.z + a.w * b.w;
    }
    lacc += b2[c];
    float mx = lacc;
    mx = fmaxf(mx, __shfl_xor_sync(0xffffffffu, mx, 1));
    mx = fmaxf(mx, __shfl_xor_sync(0xffffffffu, mx, 2));
    mx = fmaxf(mx, __shfl_xor_sync(0xffffffffu, mx, 4));
    float exv = __expf(lacc - mx);
    float s = exv;
    s += __shfl_xor_sync(0xffffffffu, s, 1);
    s += __shfl_xor_sync(0xffffffffu, s, 2);
    s += __shfl_xor_sync(0xffffffffu, s, 4);
    float lse = mx + __logf(s);
    int n = n0 + nl;
    if (n < NN) g_lp[(size_t)n * 8 + c] = lacc - lse;
}

// ---------------- launch 3 (profiled): edge MLP via HMMA tensor cores ----------------
// 256 edges/block, 8 warps; warp w owns edges [w*32, w*32+32) as two m16 tiles.
// GEMM: A[256 x 512] (built on the fly from fp16 h) @ B[512 x 64] (fp16 weights).
__global__ void __launch_bounds__(256, 2) k_edgemlp(const int* __restrict__ ei,
                                                    const float* __restrict__ w1full,
                                                    const float* __restrict__ b1,
                                                    const float* __restrict__ w2,
                                                    const float* __restrict__ b2) {
    __shared__ uint4  stg[2][512];     // 16 KB: [buf][edge]=hs row-chunk, [buf][256+edge]=hd
    __shared__ uint4  wst[2][128];     // 4 KB:  [buf] = 16x64 fp16 W chunk (pre-swizzled)
    __shared__ float4 epi[64];         // (w512, w513, b1, w2) per j
    __shared__ float  s1s[256], s2s[256];

    int tid  = threadIdx.x;
    int wid  = tid >> 5;
    int lane = tid & 31;
    int e0   = blockIdx.x * 256;

    // per-thread gather bases
    int nsrc = ei[e0 + tid];
    int ndst = ei[EE + e0 + tid];
    const uint4* pA = (const uint4*)(g_h16 + (size_t)nsrc * 256);
    const uint4* pB = (const uint4*)(g_h16 + (size_t)ndst * 256);
    {
        float a = g_logdeg[nsrc], b = g_logdeg[ndst];
        s1s[tid] = a + b; s2s[tid] = fabsf(a - b);
    }
    if (tid < 64)
        epi[tid] = make_float4(w1full[512 * 64 + tid], w1full[513 * 64 + tid],
                               b1[tid], w2[tid]);
    // preload kt=0
    stg[0][tid]       = pA[0];
    stg[0][256 + tid] = pB[0];
    if (tid < 128) wst[0][tid] = ((const uint4*)g_Wab16)[tid];
    __syncthreads();

    float acc[2][8][4];
#pragma unroll
    for (int mt = 0; mt < 2; mt++)
#pragma unroll
        for (int t = 0; t < 8; t++)
#pragma unroll
            for (int q = 0; q < 4; q++) acc[mt][t][q] = 0.0f;

    const __half* hb0 = (const __half*)stg[0];
    const __half* hb1 = (const __half*)stg[1];
    unsigned wbase0 = smem_u32(wst[0]);
    unsigned wbase1 = smem_u32(wst[1]);
    int klane = lane & 15;
    int chi   = lane >> 4;
    int xorv  = lane & 7;
    int r = lane >> 2, c = lane & 3;
    int eb = wid * 32;

    for (int kt = 0; kt < 32; kt++) {
        int buf = kt & 1;
        if (kt < 31) {
            stg[buf ^ 1][tid]       = pA[kt + 1];
            stg[buf ^ 1][256 + tid] = pB[kt + 1];
            if (tid < 128) wst[buf ^ 1][tid] = ((const uint4*)g_Wab16)[(kt + 1) * 128 + tid];
        }
        const __half* hb = buf ? hb1 : hb0;
        unsigned wbase = (buf ? wbase1 : wbase0) + (unsigned)(klane * 128);

        // build A fragments for both m-tiles
        unsigned afr[2][4];
#pragma unroll
        for (int mt = 0; mt < 2; mt++) {
            int e1 = eb + mt * 16 + r;
            int e2 = e1 + 8;
            __half hs0 = hb[e1 * 8 + c],      hd0 = hb[2048 + e1 * 8 + c];
            __half hs1 = hb[e2 * 8 + c],      hd1 = hb[2048 + e2 * 8 + c];
            __half hs2 = hb[e1 * 8 + c + 4],  hd2 = hb[2048 + e1 * 8 + c + 4];
            __half hs3 = hb[e2 * 8 + c + 4],  hd3 = hb[2048 + e2 * 8 + c + 4];
            __half2 A0 = __halves2half2(__hmul(hs0, hd0), __habs(__hsub(hs0, hd0)));
            __half2 A1 = __halves2half2(__hmul(hs1, hd1), __habs(__hsub(hs1, hd1)));
            __half2 A2 = __halves2half2(__hmul(hs2, hd2), __habs(__hsub(hs2, hd2)));
            __half2 A3 = __halves2half2(__hmul(hs3, hd3), __habs(__hsub(hs3, hd3)));
            afr[mt][0] = *(unsigned*)&A0; afr[mt][1] = *(unsigned*)&A1;
            afr[mt][2] = *(unsigned*)&A2; afr[mt][3] = *(unsigned*)&A3;
        }
#pragma unroll
        for (int t = 0; t < 4; t++) {
            unsigned b0, b1r, b2r, b3;
            unsigned addr = wbase + (unsigned)((((2 * t + chi) ^ xorv) << 4));
            asm volatile("ldmatrix.sync.aligned.m8n8.x4.trans.shared.b16 {%0,%1,%2,%3}, [%4];"
                         : "=r"(b0), "=r"(b1r), "=r"(b2r), "=r"(b3) : "r"(addr));
#pragma unroll
            for (int mt = 0; mt < 2; mt++) {
                asm volatile("mma.sync.aligned.m16n8k16.row.col.f32.f16.f16.f32 "
                             "{%0,%1,%2,%3}, {%4,%5,%6,%7}, {%8,%9}, {%0,%1,%2,%3};"
                             : "+f"(acc[mt][2 * t][0]), "+f"(acc[mt][2 * t][1]),
                               "+f"(acc[mt][2 * t][2]), "+f"(acc[mt][2 * t][3])
                             : "r"(afr[mt][0]), "r"(afr[mt][1]), "r"(afr[mt][2]), "r"(afr[mt][3]),
                               "r"(b0), "r"(b1r));
                asm volatile("mma.sync.aligned.m16n8k16.row.col.f32.f16.f16.f32 "
                             "{%0,%1,%2,%3}, {%4,%5,%6,%7}, {%8,%9}, {%0,%1,%2,%3};"
                             : "+f"(acc[mt][2 * t + 1][0]), "+f"(acc[mt][2 * t + 1][1]),
                               "+f"(acc[mt][2 * t + 1][2]), "+f"(acc[mt][2 * t + 1][3])
                             : "r"(afr[mt][0]), "r"(afr[mt][1]), "r"(afr[mt][2]), "r"(afr[mt][3]),
                               "r"(b2r), "r"(b3));
            }
        }
        __syncthreads();
    }

    // epilogue: struct terms + bias, relu, dot w2, reduce over lanes c
    float b2v = b2[0];
#pragma unroll
    for (int mt = 0; mt < 2; mt++) {
        int er  = eb + mt * 16 + r;
        int er8 = er + 8;
        float s1r = s1s[er], s2r = s2s[er];
        float s18 = s1s[er8], s28 = s2s[er8];
        float vr = 0.0f, v8 = 0.0f;
#pragma unroll
        for (int t = 0; t < 8; t++) {
#pragma unroll
            for (int u = 0; u < 2; u++) {
                float4 pp = epi[t * 8 + c * 2 + u];
                float pre  = acc[mt][t][u]     + s1r * pp.x + s2r * pp.y + pp.z;
                float pre8 = acc[mt][t][2 + u] + s18 * pp.x + s28 * pp.y + pp.z;
                vr += fmaxf(pre, 0.0f) * pp.w;
                v8 += fmaxf(pre8, 0.0f) * pp.w;
            }
        }
        vr += __shfl_xor_sync(0xffffffffu, vr, 1);
        vr += __shfl_xor_sync(0xffffffffu, vr, 2);
        v8 += __shfl_xor_sync(0xffffffffu, v8, 1);
        v8 += __shfl_xor_sync(0xffffffffu, v8, 2);
        if (c == 0) {
            g_wpre[e0 + er]  = 0.8f / (1.0f + __expf(-(vr + b2v)));
            g_wpre[e0 + er8] = 0.8f / (1.0f + __expf(-(v8 + b2v)));
        }
    }
}

// ---------------- launch 4: init (w, enorm, m0) + first A phase ----------------
__global__ void __launch_bounds__(256) k_initA(const int* __restrict__ ei,
                                               const int* __restrict__ rev) {
    __shared__ float Rs[64];
    if (threadIdx.x < 64) Rs[threadIdx.x] = g_R[threadIdx.x];
    __syncthreads();
    int e = blockIdx.x * 256 + threadIdx.x;
    float w = 0.5f * (g_wpre[e] + g_wpre[rev[e]]);
    g_w[e] = w;
    int s = ei[e], d = ei[EE + e];
    float en = rsqrtf(fmaxf(g_deg[s], 1.0f) * fmaxf(g_deg[d], 1.0f)) * 0.6931471805599453f;
    g_enorm[e] = en;
    const float4* lp4 = (const float4*)(g_lp + (size_t)s * 8);
    float4 lA = lp4[0], lB = lp4[1];
    float lps[8] = {lA.x, lA.y, lA.z, lA.w, lB.x, lB.y, lB.z, lB.w};
    float mv[8], sum = 0.0f;
#pragma unroll
    for (int c = 0; c < 8; c++) { mv[c] = __expf(lps[c]); sum += mv[c]; }
    float inv = 1.0f / sum;
#pragma unroll
    for (int c = 0; c < 8; c++) mv[c] *= inv;
    float4* m4 = (float4*)(g_m + (size_t)e * 8);
    m4[0] = make_float4(mv[0], mv[1], mv[2], mv[3]);
    m4[1] = make_float4(mv[4], mv[5], mv[6], mv[7]);
    float f[8] = {0,0,0,0,0,0,0,0};
#pragma unroll
    for (int c = 0; c < 8; c++)
#pragma unroll
        for (int dd = 0; dd < 8; dd++) f[dd] += mv[c] * exp2f(w * Rs[c * 8 + dd]);
    float lf[8];
#pragma unroll
    for (int i = 0; i < 8; i++) lf[i] = __log2f(fmaxf(f[i], 1e-12f)) * en;
    float4* lf4 = (float4*)(g_logf[0] + (size_t)e * 8);
    lf4[0] = make_float4(lf[0], lf[1], lf[2], lf[3]);
    lf4[1] = make_float4(lf[4], lf[5], lf[6], lf[7]);
    float* sp = &g_sumin[0][(size_t)d * 8];
    red_add_v4(sp,     lf[0], lf[1], lf[2], lf[3]);
    red_add_v4(sp + 4, lf[4], lf[5], lf[6], lf[7]);
}

// ---------------- BP step t ----------------
__global__ void __launch_bounds__(256) k_bpfused(const int* __restrict__ ei,
                                                 const int* __restrict__ rev,
                                                 const float* __restrict__ mlogit,
                                                 int t) {
    __shared__ float Rs[64];
    if (threadIdx.x < 64) Rs[threadIdx.x] = g_R[threadIdx.x];
    __syncthreads();
    int e = blockIdx.x * 256 + threadIdx.x;
    int p = t & 1;
    float alpha = 1.5f / (1.0f + __expf(-mlogit[0]));
    int s = ei[e], d = ei[EE + e];
    size_t r = (size_t)rev[e];
    const float4* si4 = (const float4*)(g_sumin[t] + (size_t)s * 8);
    const float4* lr4 = (const float4*)(g_logf[p] + r * 8);
    const float4* lp4 = (const float4*)(g_lp + (size_t)s * 8);
    float4* m4 = (float4*)(g_m + (size_t)e * 8);
    float4 siA = si4[0], siB = si4[1];
    float4 lrA = lr4[0], lrB = lr4[1];
    float4 lpA = lp4[0], lpB = lp4[1];
    float4 mA = m4[0], mB = m4[1];
    float tt[8];
    tt[0] = lpA.x + alpha * (siA.x - lrA.x); tt[1] = lpA.y + alpha * (siA.y - lrA.y);
    tt[2] = lpA.z + alpha * (siA.z - lrA.z); tt[3] = lpA.w + alpha * (siA.w - lrA.w);
    tt[4] = lpB.x + alpha * (siB.x - lrB.x); tt[5] = lpB.y + alpha * (siB.y - lrB.y);
    tt[6] = lpB.z + alpha * (siB.z - lrB.z); tt[7] = lpB.w + alpha * (siB.w - lrB.w);
    float mx = -1e30f;
#pragma unroll
    for (int i = 0; i < 8; i++) mx = fmaxf(mx, tt[i]);
    float ex[8], sum = 0.0f;
#pragma unroll
    for (int i = 0; i < 8; i++) { ex[i] = __expf(tt[i] - mx); sum += ex[i]; }
    float inv = 1.0f / sum;
    float mo[8] = {mA.x, mA.y, mA.z, mA.w, mB.x, mB.y, mB.z, mB.w};
    float mn[8], s2 = 0.0f;
#pragma unroll
    for (int i = 0; i < 8; i++) {
        mn[i] = fmaxf(0.8f * mo[i] + 0.2f * ex[i] * inv, 1e-12f);
        s2 += mn[i];
    }
    float inv2 = 1.0f / s2;
#pragma unroll
    for (int i = 0; i < 8; i++) mn[i] *= inv2;
    m4[0] = make_float4(mn[0], mn[1], mn[2], mn[3]);
    m4[1] = make_float4(mn[4], mn[5], mn[6], mn[7]);
    float w = g_w[e], en = g_enorm[e];
    float f[8] = {0,0,0,0,0,0,0,0};
#pragma unroll
    for (int c = 0; c < 8; c++)
#pragma unroll
        for (int dd = 0; dd < 8; dd++) f[dd] += mn[c] * exp2f(w * Rs[c * 8 + dd]);
    float lf[8];
#pragma unroll
    for (int i = 0; i < 8; i++) lf[i] = __log2f(fmaxf(f[i], 1e-12f)) * en;
    float4* lf4 = (float4*)(g_logf[p ^ 1] + (size_t)e * 8);
    lf4[0] = make_float4(lf[0], lf[1], lf[2], lf[3]);
    lf4[1] = make_float4(lf[4], lf[5], lf[6], lf[7]);
    float* sp = &g_sumin[t + 1][(size_t)d * 8];
    red_add_v4(sp,     lf[0], lf[1], lf[2], lf[3]);
    red_add_v4(sp + 4, lf[4], lf[5], lf[6], lf[7]);
}

// ---------------- final beliefs ----------------
__global__ void k_belief(const float* __restrict__ mlogit, float* __restrict__ out) {
    int n = blockIdx.x * blockDim.x + threadIdx.x;
    if (n >= NN) return;
    float alpha = 1.5f / (1.0f + __expf(-mlogit[0]));
    float t[8], mx = -1e30f;
#pragma unroll
    for (int c = 0; c < 8; c++) {
        t[c] = g_lp[(size_t)n * 8 + c] + alpha * g_sumin[10][(size_t)n * 8 + c];
        mx = fmaxf(mx, t[c]);
    }
    float sum = 0.0f;
#pragma unroll
    for (int c = 0; c < 8; c++) { t[c] = __expf(t[c] - mx); sum += t[c]; }
    float inv = 1.0f / sum;
#pragma unroll
    for (int c = 0; c < 8; c++) out[(size_t)n * 8 + c] = t[c] * inv;
}

// ---------------- launch ----------------
extern "C" void kernel_launch(void* const* d_in, const int* in_sizes, int n_in,
                              void* d_out, int out_size) {
    const float* x       = (const float*)d_in[0];
    const int*   ei      = (const int*)d_in[1];
    const int*   rev     = (const int*)d_in[2];
    const float* enc_w1  = (const float*)d_in[3];
    const float* enc_b1  = (const float*)d_in[4];
    const float* enc_w2  = (const float*)d_in[5];
    const float* enc_b2  = (const float*)d_in[6];
    const float* edge_w1 = (const float*)d_in[7];
    const float* edge_b1 = (const float*)d_in[8];
    const float* edge_w2 = (const float*)d_in[9];
    const float* edge_b2 = (const float*)d_in[10];
    const float* R_raw   = (const float*)d_in[11];
    const float* rsl     = (const float*)d_in[12];
    const float* mlogit  = (const float*)d_in[13];
    float* out = (float*)d_out;

    k_prep_all<<<(11 * NN * 8 + 255) / 256, 256>>>(R_raw, rsl, edge_w1);      // 0
    k_deg<<<(EE + 255) / 256, 256>>>(ei);                                     // 1
    k_encoder<<<(NN + 31) / 32, 256>>>(x, enc_w1, enc_b1, enc_w2, enc_b2);    // 2
    k_edgemlp<<<EE / 256, 256>>>(ei, edge_w1, edge_b1, edge_w2, edge_b2);     // 3 <- profiled
    k_initA<<<EE / 256, 256>>>(ei, rev);                                      // 4
    for (int t = 0; t < 10; t++)
        k_bpfused<<<EE / 256, 256>>>(ei, rev, mlogit, t);                     // 5..14
    k_belief<<<(NN + 255) / 256, 256>>>(mlogit, out);                         // 15
}

// round 7
// speedup vs baseline: 6.3863x; 1.1744x over previous
#include <cuda_runtime.h>
#include <cuda_fp16.h>
#include <math.h>

#define NN   50000
#define E2n  400000
#define EE   800000
#define HID  256

typedef unsigned long long ull;
typedef unsigned int uint;

// ---------------- scratch ----------------
__device__ __align__(16) __half g_h16[(size_t)NN * 256];     // 25.6 MB
__device__ __align__(16) float g_lp[(size_t)NN * 8];
__device__ float g_deg[NN];
__device__ float g_logdeg[NN];
__device__ float g_wpre[E2n];
__device__ float g_w[E2n];
__device__ float g_enorm[E2n];                               // rsqrt(..)*ln2
__device__ __align__(16) float g_m[(size_t)EE * 8];
__device__ __align__(32) float g_logf[2][(size_t)EE * 8];
__device__ __align__(32) float g_sumin[11][(size_t)NN * 8];  // pre-zeroed
__device__ __align__(16) float g_R[64];                      // R * log2(e)
__device__ __align__(16) __half g_Wab16[512 * 64];           // edge_w1 interleaved+swizzled

// ---------------- helpers ----------------
__device__ __forceinline__ ull pack2(float x, float y) {
    ull r; asm("mov.b64 %0, {%1,%2};" : "=l"(r) : "f"(x), "f"(y)); return r;
}
__device__ __forceinline__ float2 unpack2(ull v) {
    float2 r; asm("mov.b64 {%0,%1}, %2;" : "=f"(r.x), "=f"(r.y) : "l"(v)); return r;
}
__device__ __forceinline__ void fma2(ull& d, ull a, ull b) {
    asm("fma.rn.f32x2 %0, %1, %2, %3;" : "=l"(d) : "l"(a), "l"(b), "l"(d));
}
__device__ __forceinline__ void red_add_v4(float* p, float a, float b, float c, float d) {
    ull gp = (ull)__cvta_generic_to_global(p);
    asm volatile("red.global.add.v4.f32 [%0], {%1,%2,%3,%4};"
                 :: "l"(gp), "f"(a), "f"(b), "f"(c), "f"(d) : "memory");
}
__device__ __forceinline__ unsigned smem_u32(const void* p) {
    unsigned a;
    asm("{ .reg .u64 t; cvta.to.shared.u64 t, %1; cvt.u32.u64 %0, t; }" : "=r"(a) : "l"(p));
    return a;
}
__device__ __forceinline__ void ldsm4t(uint& a, uint& b, uint& c, uint& d, uint addr) {
    asm volatile("ldmatrix.sync.aligned.m8n8.x4.trans.shared.b16 {%0,%1,%2,%3}, [%4];"
                 : "=r"(a), "=r"(b), "=r"(c), "=r"(d) : "r"(addr));
}
__device__ __forceinline__ void mma16816(float* acc, const uint* a, uint b0, uint b1) {
    asm volatile("mma.sync.aligned.m16n8k16.row.col.f32.f16.f16.f32 "
                 "{%0,%1,%2,%3}, {%4,%5,%6,%7}, {%8,%9}, {%0,%1,%2,%3};"
                 : "+f"(acc[0]), "+f"(acc[1]), "+f"(acc[2]), "+f"(acc[3])
                 : "r"(a[0]), "r"(a[1]), "r"(a[2]), "r"(a[3]), "r"(b0), "r"(b1));
}

// ---------------- launch 0: prep ----------------
__global__ void k_prep_all(const float* __restrict__ R_raw, const float* __restrict__ rsl,
                           const float* __restrict__ ew1) {
    int i = blockIdx.x * 256 + threadIdx.x;
    if (i < 11 * NN * 8) ((float*)g_sumin)[i] = 0.0f;
    if (i < NN) g_deg[i] = 0.0f;
    if (i < 512 * 64) {
        int k = i >> 6, j = i & 63;
        int c = j >> 3, u = j & 7;
        int pos = (k << 6) + (((c ^ (k & 7)) << 3) + u);
        int hc = k >> 1;
        float v = (k & 1) ? ew1[(256 + hc) * 64 + j] : ew1[hc * 64 + j];
        g_Wab16[pos] = __float2half_rn(v);
    }
    if (i < 64) {
        int r = i >> 3, c = i & 7;
        float v = 0.5f * (R_raw[r * 8 + c] + R_raw[c * 8 + r]);
        float s = log1pf(expf(rsl[0])) + 1e-6f;
        g_R[i] = s * tanhf(v) * 1.44269504088896f;
    }
}

// ---------------- launch 1: degree ----------------
__global__ void k_deg(const int* __restrict__ ei) {
    int e = blockIdx.x * blockDim.x + threadIdx.x;
    if (e < EE) atomicAdd(&g_deg[ei[e]], 1.0f);
}

// ---------------- launch 2: R4-proven encoder (FFMA2) + logdeg + fused logits ----------------
__global__ void __launch_bounds__(256) k_encoder(const float* __restrict__ x,
                                                 const float* __restrict__ w1,
                                                 const float* __restrict__ b1,
                                                 const float* __restrict__ w2,
                                                 const float* __restrict__ b2) {
    __shared__ float2 xs2[64][16];
    __shared__ float  hs[32][260];
    __shared__ float  w2t[8][260];
    int tid = threadIdx.x;
    if (blockIdx.x < (NN + 255) / 256) {
        int n = blockIdx.x * 256 + tid;
        if (n < NN) g_logdeg[n] = __logf(g_deg[n] + 1.0f);
    }
    for (int i = tid; i < 2048; i += 256) w2t[i & 7][i >> 3] = w2[i];

    int n0 = blockIdx.x * 32;
    int j  = tid;
    ull acc[16];
#pragma unroll
    for (int i = 0; i < 16; i++) acc[i] = 0ull;

    int sn = tid >> 3, sq = tid & 7;
    int gn = min(n0 + sn, NN - 1);
    const float4* xr = (const float4*)(x + (size_t)gn * 512 + sq * 8);
    int pr = sn & 15, hf = sn >> 4;

    for (int kt = 0; kt < 8; kt++) {
        __syncthreads();
        {
            float4 a = xr[kt * 16 + 0];
            float4 b = xr[kt * 16 + 1];
            float vals[8] = {a.x, a.y, a.z, a.w, b.x, b.y, b.z, b.w};
#pragma unroll
            for (int i = 0; i < 8; i++)
                ((float*)&xs2[sq * 8 + i][pr])[hf] = vals[i];
        }
        __syncthreads();
#pragma unroll 4
        for (int k = 0; k < 64; k++) {
            float wv = w1[(kt * 64 + k) * 256 + j];
            ull wp = pack2(wv, wv);
            const longlong2* row = (const longlong2*)xs2[k];
#pragma unroll
            for (int p2 = 0; p2 < 8; p2++) {
                longlong2 xv = row[p2];
                fma2(acc[p2 * 2 + 0], (ull)xv.x, wp);
                fma2(acc[p2 * 2 + 1], (ull)xv.y, wp);
            }
        }
    }
    float bb = b1[j];
#pragma unroll
    for (int i = 0; i < 16; i++) {
        float2 v = unpack2(acc[i]);
        float hlo = fmaxf(v.x + bb, 0.0f);
        float hhi = fmaxf(v.y + bb, 0.0f);
        hs[i][j] = hlo; hs[16 + i][j] = hhi;
        int nlo = n0 + i, nhi = n0 + 16 + i;
        if (nlo < NN) g_h16[(size_t)nlo * 256 + j] = __float2half_rn(hlo);
        if (nhi < NN) g_h16[(size_t)nhi * 256 + j] = __float2half_rn(hhi);
    }
    __syncthreads();
    int nl = tid >> 3, c = tid & 7;
    float lacc = 0.0f;
    const float4* hrow = (const float4*)hs[nl];
    const float4* wrow = (const float4*)w2t[c];
#pragma unroll 8
    for (int q = 0; q < 64; q++) {
        float4 a = hrow[q], b = wrow[q];
        lacc += a.x * b.x + a.y * b.y + a.z * b.z + a.w * b.w;
    }
    lacc += b2[c];
    float mx = lacc;
    mx = fmaxf(mx, __shfl_xor_sync(0xffffffffu, mx, 1));
    mx = fmaxf(mx, __shfl_xor_sync(0xffffffffu, mx, 2));
    mx = fmaxf(mx, __shfl_xor_sync(0xffffffffu, mx, 4));
    float exv = __expf(lacc - mx);
    float s = exv;
    s += __shfl_xor_sync(0xffffffffu, s, 1);
    s += __shfl_xor_sync(0xffffffffu, s, 2);
    s += __shfl_xor_sync(0xffffffffu, s, 4);
    float lse = mx + __logf(s);
    int n = n0 + nl;
    if (n < NN) g_lp[(size_t)n * 8 + c] = lacc - lse;
}

// ---------------- launch 3 (profiled): edge MLP over E2 undirected pairs, HMMA ----------------
__global__ void __launch_bounds__(256, 2) k_edgemlp(const int* __restrict__ ei,
                                                    const float* __restrict__ w1full,
                                                    const float* __restrict__ b1,
                                                    const float* __restrict__ w2,
                                                    const float* __restrict__ b2) {
    __shared__ uint4  stg[2][512];
    __shared__ uint4  wst[2][128];
    __shared__ float4 epi[64];
    __shared__ float  s1s[256], s2s[256];

    int tid  = threadIdx.x;
    int wid  = tid >> 5;
    int lane = tid & 31;
    int e0   = blockIdx.x * 256;

    int nsrc = ei[e0 + tid];            // indices < E2n+128 < EE: in-range reads
    int ndst = ei[EE + e0 + tid];
    const uint4* pA = (const uint4*)(g_h16 + (size_t)nsrc * 256);
    const uint4* pB = (const uint4*)(g_h16 + (size_t)ndst * 256);
    {
        float a = g_logdeg[nsrc], b = g_logdeg[ndst];
        s1s[tid] = a + b; s2s[tid] = fabsf(a - b);
    }
    if (tid < 64)
        epi[tid] = make_float4(w1full[512 * 64 + tid], w1full[513 * 64 + tid],
                               b1[tid], w2[tid]);
    stg[0][tid]       = pA[0];
    stg[0][256 + tid] = pB[0];
    if (tid < 128) wst[0][tid] = ((const uint4*)g_Wab16)[tid];
    __syncthreads();

    float acc[2][8][4];
#pragma unroll
    for (int mt = 0; mt < 2; mt++)
#pragma unroll
        for (int t = 0; t < 8; t++)
#pragma unroll
            for (int q = 0; q < 4; q++) acc[mt][t][q] = 0.0f;

    const __half* hb0 = (const __half*)stg[0];
    const __half* hb1 = (const __half*)stg[1];
    unsigned wbase0 = smem_u32(wst[0]);
    unsigned wbase1 = smem_u32(wst[1]);
    int klane = lane & 15;
    int chi   = lane >> 4;
    int xorv  = lane & 7;
    int r = lane >> 2, c = lane & 3;
    int eb = wid * 32;

    for (int kt = 0; kt < 32; kt++) {
        int buf = kt & 1;
        if (kt < 31) {
            stg[buf ^ 1][tid]       = pA[kt + 1];
            stg[buf ^ 1][256 + tid] = pB[kt + 1];
            if (tid < 128) wst[buf ^ 1][tid] = ((const uint4*)g_Wab16)[(kt + 1) * 128 + tid];
        }
        const __half* hb = buf ? hb1 : hb0;
        unsigned wbase = (buf ? wbase1 : wbase0) + (unsigned)(klane * 128);

        unsigned afr[2][4];
#pragma unroll
        for (int mt = 0; mt < 2; mt++) {
            int e1 = eb + mt * 16 + r;
            int e2 = e1 + 8;
            __half hs0 = hb[e1 * 8 + c],      hd0 = hb[2048 + e1 * 8 + c];
            __half hs1 = hb[e2 * 8 + c],      hd1 = hb[2048 + e2 * 8 + c];
            __half hs2 = hb[e1 * 8 + c + 4],  hd2 = hb[2048 + e1 * 8 + c + 4];
            __half hs3 = hb[e2 * 8 + c + 4],  hd3 = hb[2048 + e2 * 8 + c + 4];
            __half2 A0 = __halves2half2(__hmul(hs0, hd0), __habs(__hsub(hs0, hd0)));
            __half2 A1 = __halves2half2(__hmul(hs1, hd1), __habs(__hsub(hs1, hd1)));
            __half2 A2 = __halves2half2(__hmul(hs2, hd2), __habs(__hsub(hs2, hd2)));
            __half2 A3 = __halves2half2(__hmul(hs3, hd3), __habs(__hsub(hs3, hd3)));
            afr[mt][0] = *(unsigned*)&A0; afr[mt][1] = *(unsigned*)&A1;
            afr[mt][2] = *(unsigned*)&A2; afr[mt][3] = *(unsigned*)&A3;
        }
#pragma unroll
        for (int t = 0; t < 4; t++) {
            unsigned b0, b1r, b2r, b3;
            unsigned addr = wbase + (unsigned)((((2 * t + chi) ^ xorv) << 4));
            ldsm4t(b0, b1r, b2r, b3, addr);
#pragma unroll
            for (int mt = 0; mt < 2; mt++) {
                mma16816(acc[mt][2 * t],     afr[mt], b0,  b1r);
                mma16816(acc[mt][2 * t + 1], afr[mt], b2r, b3);
            }
        }
        __syncthreads();
    }

    float b2v = b2[0];
#pragma unroll
    for (int mt = 0; mt < 2; mt++) {
        int er  = eb + mt * 16 + r;
        int er8 = er + 8;
        float s1r = s1s[er], s2r = s2s[er];
        float s18 = s1s[er8], s28 = s2s[er8];
        float vr = 0.0f, v8 = 0.0f;
#pragma unroll
        for (int t = 0; t < 8; t++) {
#pragma unroll
            for (int u = 0; u < 2; u++) {
                float4 pp = epi[t * 8 + c * 2 + u];
                float pre  = acc[mt][t][u]     + s1r * pp.x + s2r * pp.y + pp.z;
                float pre8 = acc[mt][t][2 + u] + s18 * pp.x + s28 * pp.y + pp.z;
                vr += fmaxf(pre, 0.0f) * pp.w;
                v8 += fmaxf(pre8, 0.0f) * pp.w;
            }
        }
        vr += __shfl_xor_sync(0xffffffffu, vr, 1);
        vr += __shfl_xor_sync(0xffffffffu, vr, 2);
        v8 += __shfl_xor_sync(0xffffffffu, v8, 1);
        v8 += __shfl_xor_sync(0xffffffffu, v8, 2);
        if (c == 0) {
            if (e0 + er  < E2n) g_wpre[e0 + er]  = 0.8f / (1.0f + __expf(-(vr + b2v)));
            if (e0 + er8 < E2n) g_wpre[e0 + er8] = 0.8f / (1.0f + __expf(-(v8 + b2v)));
        }
    }
}

// ---------------- launch 4: pair init + first A phase ----------------
__global__ void __launch_bounds__(256) k_initA(const int* __restrict__ ei) {
    __shared__ float Rs[64];
    if (threadIdx.x < 64) Rs[threadIdx.x] = g_R[threadIdx.x];
    __syncthreads();
    int p = blockIdx.x * 256 + threadIdx.x;
    if (p >= E2n) return;
    float w = g_wpre[p];
    g_w[p] = w;
    int s = ei[p], d = ei[EE + p];
    float en = rsqrtf(fmaxf(g_deg[s], 1.0f) * fmaxf(g_deg[d], 1.0f)) * 0.6931471805599453f;
    g_enorm[p] = en;
    const float4* ls4 = (const float4*)(g_lp + (size_t)s * 8);
    const float4* ld4 = (const float4*)(g_lp + (size_t)d * 8);
    float4 sA = ls4[0], sB = ls4[1], dA = ld4[0], dB = ld4[1];
    float mf[8] = {sA.x, sA.y, sA.z, sA.w, sB.x, sB.y, sB.z, sB.w};
    float mb[8] = {dA.x, dA.y, dA.z, dA.w, dB.x, dB.y, dB.z, dB.w};
    float sf = 0.0f, sb = 0.0f;
#pragma unroll
    for (int c = 0; c < 8; c++) { mf[c] = __expf(mf[c]); sf += mf[c];
                                  mb[c] = __expf(mb[c]); sb += mb[c]; }
    float isf = 1.0f / sf, isb = 1.0f / sb;
#pragma unroll
    for (int c = 0; c < 8; c++) { mf[c] *= isf; mb[c] *= isb; }
    float4* mf4 = (float4*)(g_m + (size_t)p * 8);
    float4* mb4 = (float4*)(g_m + (size_t)(p + E2n) * 8);
    mf4[0] = make_float4(mf[0], mf[1], mf[2], mf[3]);
    mf4[1] = make_float4(mf[4], mf[5], mf[6], mf[7]);
    mb4[0] = make_float4(mb[0], mb[1], mb[2], mb[3]);
    mb4[1] = make_float4(mb[4], mb[5], mb[6], mb[7]);
    float ff[8] = {0,0,0,0,0,0,0,0}, fb[8] = {0,0,0,0,0,0,0,0};
#pragma unroll
    for (int c = 0; c < 8; c++)
#pragma unroll
        for (int dd = 0; dd < 8; dd++) {
            float kv = exp2f(w * Rs[c * 8 + dd]);
            ff[dd] += mf[c] * kv;
            fb[dd] += mb[c] * kv;
        }
    float lff[8], lfb[8];
#pragma unroll
    for (int i = 0; i < 8; i++) {
        lff[i] = __log2f(fmaxf(ff[i], 1e-12f)) * en;
        lfb[i] = __log2f(fmaxf(fb[i], 1e-12f)) * en;
    }
    float4* of = (float4*)(g_logf[0] + (size_t)p * 8);
    float4* ob = (float4*)(g_logf[0] + (size_t)(p + E2n) * 8);
    of[0] = make_float4(lff[0], lff[1], lff[2], lff[3]);
    of[1] = make_float4(lff[4], lff[5], lff[6], lff[7]);
    ob[0] = make_float4(lfb[0], lfb[1], lfb[2], lfb[3]);
    ob[1] = make_float4(lfb[4], lfb[5], lfb[6], lfb[7]);
    float* spd = &g_sumin[0][(size_t)d * 8];
    float* sps = &g_sumin[0][(size_t)s * 8];
    red_add_v4(spd,     lff[0], lff[1], lff[2], lff[3]);
    red_add_v4(spd + 4, lff[4], lff[5], lff[6], lff[7]);
    red_add_v4(sps,     lfb[0], lfb[1], lfb[2], lfb[3]);
    red_add_v4(sps + 4, lfb[4], lfb[5], lfb[6], lfb[7]);
}

// ---------------- BP step t (pairs): B(t) then A(t+1) ----------------
__global__ void __launch_bounds__(256) k_bp(const int* __restrict__ ei,
                                            const float* __restrict__ mlogit, int t) {
    __shared__ float Rs[64];
    if (threadIdx.x < 64) Rs[threadIdx.x] = g_R[threadIdx.x];
    __syncthreads();
    int p = blockIdx.x * 256 + threadIdx.x;
    if (p >= E2n) return;
    int pr = t & 1;
    float alpha = 1.5f / (1.0f + __expf(-mlogit[0]));
    int s = ei[p], d = ei[EE + p];
    float w = g_w[p], en = g_enorm[p];
    const float4* sis4 = (const float4*)(g_sumin[t] + (size_t)s * 8);
    const float4* sid4 = (const float4*)(g_sumin[t] + (size_t)d * 8);
    const float4* ls4  = (const float4*)(g_lp + (size_t)s * 8);
    const float4* ld4  = (const float4*)(g_lp + (size_t)d * 8);
    const float4* lff4 = (const float4*)(g_logf[pr] + (size_t)p * 8);
    const float4* lfb4 = (const float4*)(g_logf[pr] + (size_t)(p + E2n) * 8);
    float4* mf4 = (float4*)(g_m + (size_t)p * 8);
    float4* mb4 = (float4*)(g_m + (size_t)(p + E2n) * 8);

    float4 sisA = sis4[0], sisB = sis4[1], sidA = sid4[0], sidB = sid4[1];
    float4 lsA = ls4[0], lsB = ls4[1], ldA = ld4[0], ldB = ld4[1];
    float4 lfA = lff4[0], lfB = lff4[1], lbA = lfb4[0], lbB = lfb4[1];
    float sis[8] = {sisA.x, sisA.y, sisA.z, sisA.w, sisB.x, sisB.y, sisB.z, sisB.w};
    float sid[8] = {sidA.x, sidA.y, sidA.z, sidA.w, sidB.x, sidB.y, sidB.z, sidB.w};
    float lps[8] = {lsA.x, lsA.y, lsA.z, lsA.w, lsB.x, lsB.y, lsB.z, lsB.w};
    float lpd[8] = {ldA.x, ldA.y, ldA.z, ldA.w, ldB.x, ldB.y, ldB.z, ldB.w};
    float lfp[8] = {lfA.x, lfA.y, lfA.z, lfA.w, lfB.x, lfB.y, lfB.z, lfB.w};
    float lbp[8] = {lbA.x, lbA.y, lbA.z, lbA.w, lbB.x, lbB.y, lbB.z, lbB.w};

    float tf[8], tb[8], mxf = -1e30f, mxb = -1e30f;
#pragma unroll
    for (int i = 0; i < 8; i++) {
        tf[i] = lps[i] + alpha * (sis[i] - lbp[i]);
        tb[i] = lpd[i] + alpha * (sid[i] - lfp[i]);
        mxf = fmaxf(mxf, tf[i]); mxb = fmaxf(mxb, tb[i]);
    }
    float ssf = 0.0f, ssb = 0.0f;
#pragma unroll
    for (int i = 0; i < 8; i++) {
        tf[i] = __expf(tf[i] - mxf); ssf += tf[i];
        tb[i] = __expf(tb[i] - mxb); ssb += tb[i];
    }
    float ivf = 0.2f / ssf, ivb = 0.2f / ssb;
    float4 mfA = mf4[0], mfB = mf4[1], mbA = mb4[0], mbB = mb4[1];
    float mf[8] = {mfA.x, mfA.y, mfA.z, mfA.w, mfB.x, mfB.y, mfB.z, mfB.w};
    float mb[8] = {mbA.x, mbA.y, mbA.z, mbA.w, mbB.x, mbB.y, mbB.z, mbB.w};
    float s2f = 0.0f, s2b = 0.0f;
#pragma unroll
    for (int i = 0; i < 8; i++) {
        mf[i] = fmaxf(0.8f * mf[i] + tf[i] * ivf, 1e-12f); s2f += mf[i];
        mb[i] = fmaxf(0.8f * mb[i] + tb[i] * ivb, 1e-12f); s2b += mb[i];
    }
    float i2f = 1.0f / s2f, i2b = 1.0f / s2b;
#pragma unroll
    for (int i = 0; i < 8; i++) { mf[i] *= i2f; mb[i] *= i2b; }
    mf4[0] = make_float4(mf[0], mf[1], mf[2], mf[3]);
    mf4[1] = make_float4(mf[4], mf[5], mf[6], mf[7]);
    mb4[0] = make_float4(mb[0], mb[1], mb[2], mb[3]);
    mb4[1] = make_float4(mb[4], mb[5], mb[6], mb[7]);

    float ff[8] = {0,0,0,0,0,0,0,0}, fb[8] = {0,0,0,0,0,0,0,0};
#pragma unroll
    for (int c = 0; c < 8; c++)
#pragma unroll
        for (int dd = 0; dd < 8; dd++) {
            float kv = exp2f(w * Rs[c * 8 + dd]);
            ff[dd] += mf[c] * kv;
            fb[dd] += mb[c] * kv;
        }
    float lff[8], lfb[8];
#pragma unroll
    for (int i = 0; i < 8; i++) {
        lff[i] = __log2f(fmaxf(ff[i], 1e-12f)) * en;
        lfb[i] = __log2f(fmaxf(fb[i], 1e-12f)) * en;
    }
    float4* of = (float4*)(g_logf[pr ^ 1] + (size_t)p * 8);
    float4* ob = (float4*)(g_logf[pr ^ 1] + (size_t)(p + E2n) * 8);
    of[0] = make_float4(lff[0], lff[1], lff[2], lff[3]);
    of[1] = make_float4(lff[4], lff[5], lff[6], lff[7]);
    ob[0] = make_float4(lfb[0], lfb[1], lfb[2], lfb[3]);
    ob[1] = make_float4(lfb[4], lfb[5], lfb[6], lfb[7]);
    float* spd = &g_sumin[t + 1][(size_t)d * 8];
    float* sps = &g_sumin[t + 1][(size_t)s * 8];
    red_add_v4(spd,     lff[0], lff[1], lff[2], lff[3]);
    red_add_v4(spd + 4, lff[4], lff[5], lff[6], lff[7]);
    red_add_v4(sps,     lfb[0], lfb[1], lfb[2], lfb[3]);
    red_add_v4(sps + 4, lfb[4], lfb[5], lfb[6], lfb[7]);
}

// ---------------- final beliefs ----------------
__global__ void k_belief(const float* __restrict__ mlogit, float* __restrict__ out) {
    int n = blockIdx.x * blockDim.x + threadIdx.x;
    if (n >= NN) return;
    float alpha = 1.5f / (1.0f + __expf(-mlogit[0]));
    float t[8], mx = -1e30f;
#pragma unroll
    for (int c = 0; c < 8; c++) {
        t[c] = g_lp[(size_t)n * 8 + c] + alpha * g_sumin[10][(size_t)n * 8 + c];
        mx = fmaxf(mx, t[c]);
    }
    float sum = 0.0f;
#pragma unroll
    for (int c = 0; c < 8; c++) { t[c] = __expf(t[c] - mx); sum += t[c]; }
    float inv = 1.0f / sum;
#pragma unroll
    for (int c = 0; c < 8; c++) out[(size_t)n * 8 + c] = t[c] * inv;
}

// ---------------- launch ----------------
extern "C" void kernel_launch(void* const* d_in, const int* in_sizes, int n_in,
                              void* d_out, int out_size) {
    const float* x       = (const float*)d_in[0];
    const int*   ei      = (const int*)d_in[1];
    const float* enc_w1  = (const float*)d_in[3];
    const float* enc_b1  = (const float*)d_in[4];
    const float* enc_w2  = (const float*)d_in[5];
    const float* enc_b2  = (const float*)d_in[6];
    const float* edge_w1 = (const float*)d_in[7];
    const float* edge_b1 = (const float*)d_in[8];
    const float* edge_w2 = (const float*)d_in[9];
    const float* edge_b2 = (const float*)d_in[10];
    const float* R_raw   = (const float*)d_in[11];
    const float* rsl     = (const float*)d_in[12];
    const float* mlogit  = (const float*)d_in[13];
    float* out = (float*)d_out;

    int PB = (E2n + 255) / 256;   // 1563 pair blocks

    k_prep_all<<<(11 * NN * 8 + 255) / 256, 256>>>(R_raw, rsl, edge_w1);         // 0
    k_deg<<<(EE + 255) / 256, 256>>>(ei);                                        // 1
    k_encoder<<<(NN + 31) / 32, 256>>>(x, enc_w1, enc_b1, enc_w2, enc_b2);       // 2
    k_edgemlp<<<PB, 256>>>(ei, edge_w1, edge_b1, edge_w2, edge_b2);              // 3 <- profiled
    k_initA<<<PB, 256>>>(ei);                                                    // 4
    for (int t = 0; t < 10; t++)
        k_bp<<<PB, 256>>>(ei, mlogit, t);                                        // 5..14
    k_belief<<<(NN + 255) / 256, 256>>>(mlogit, out);                            // 15
}

// round 8
// speedup vs baseline: 9.2544x; 1.4491x over previous
#include <cuda_runtime.h>
#include <cuda_fp16.h>
#include <math.h>

#define NN   50000
#define E2n  400000
#define EE   800000

typedef unsigned long long ull;
typedef unsigned int uint;

// ---------------- scratch ----------------
__device__ __align__(16) __half g_h16[(size_t)NN * 256];     // 25.6 MB
__device__ __align__(16) float g_lp[(size_t)NN * 8];
__device__ float g_deg[NN];
__device__ float g_logdeg[NN];
__device__ float g_wpre[E2n];
__device__ float g_w[E2n];
__device__ float g_enorm[E2n];                               // rsqrt(..)*ln2
__device__ __align__(16) float g_m[(size_t)EE * 8];
__device__ __align__(32) float g_logf[2][(size_t)EE * 8];
__device__ __align__(32) float g_sumin[11][(size_t)NN * 8];  // pre-zeroed
__device__ __align__(16) float g_R[64];                      // R * log2(e)
__device__ __align__(16) __half g_Wab16[512 * 64];           // edge_w1 interleaved+swizzled
__device__ __align__(16) __half g_w1h[512 * 256];            // enc_w1 hi
__device__ __align__(16) __half g_w1l[512 * 256];            // enc_w1 lo residual

// ---------------- helpers ----------------
__device__ __forceinline__ void red_add_v4(float* p, float a, float b, float c, float d) {
    ull gp = (ull)__cvta_generic_to_global(p);
    asm volatile("red.global.add.v4.f32 [%0], {%1,%2,%3,%4};"
                 :: "l"(gp), "f"(a), "f"(b), "f"(c), "f"(d) : "memory");
}
__device__ __forceinline__ unsigned smem_u32(const void* p) {
    unsigned a;
    asm("{ .reg .u64 t; cvta.to.shared.u64 t, %1; cvt.u32.u64 %0, t; }" : "=r"(a) : "l"(p));
    return a;
}
__device__ __forceinline__ void ldsm4(uint& a, uint& b, uint& c, uint& d, uint addr) {
    asm volatile("ldmatrix.sync.aligned.m8n8.x4.shared.b16 {%0,%1,%2,%3}, [%4];"
                 : "=r"(a), "=r"(b), "=r"(c), "=r"(d) : "r"(addr));
}
__device__ __forceinline__ void ldsm4t(uint& a, uint& b, uint& c, uint& d, uint addr) {
    asm volatile("ldmatrix.sync.aligned.m8n8.x4.trans.shared.b16 {%0,%1,%2,%3}, [%4];"
                 : "=r"(a), "=r"(b), "=r"(c), "=r"(d) : "r"(addr));
}
__device__ __forceinline__ void mma16816(float* acc, const uint* a, uint b0, uint b1) {
    asm volatile("mma.sync.aligned.m16n8k16.row.col.f32.f16.f16.f32 "
                 "{%0,%1,%2,%3}, {%4,%5,%6,%7}, {%8,%9}, {%0,%1,%2,%3};"
                 : "+f"(acc[0]), "+f"(acc[1]), "+f"(acc[2]), "+f"(acc[3])
                 : "r"(a[0]), "r"(a[1]), "r"(a[2]), "r"(a[3]), "r"(b0), "r"(b1));
}

// ---------------- launch 0: prep ----------------
__global__ void k_prep_all(const float* __restrict__ R_raw, const float* __restrict__ rsl,
                           const float* __restrict__ ew1, const float* __restrict__ encw1) {
    int i = blockIdx.x * 256 + threadIdx.x;
    if (i < 11 * NN * 8) ((float*)g_sumin)[i] = 0.0f;
    if (i < NN) g_deg[i] = 0.0f;
    if (i < 512 * 64) {
        int k = i >> 6, j = i & 63;
        int c = j >> 3, u = j & 7;
        int pos = (k << 6) + (((c ^ (k & 7)) << 3) + u);
        int hc = k >> 1;
        float v = (k & 1) ? ew1[(256 + hc) * 64 + j] : ew1[hc * 64 + j];
        g_Wab16[pos] = __float2half_rn(v);
    }
    if (i < 512 * 256) {
        float v = encw1[i];
        __half h = __float2half_rn(v);
        g_w1h[i] = h;
        g_w1l[i] = __float2half_rn(v - __half2float(h));
    }
    if (i < 64) {
        int r = i >> 3, c = i & 7;
        float v = 0.5f * (R_raw[r * 8 + c] + R_raw[c * 8 + r]);
        float s = log1pf(expf(rsl[0])) + 1e-6f;
        g_R[i] = s * tanhf(v) * 1.44269504088896f;
    }
}

// ---------------- launch 1: degree ----------------
__global__ void k_deg(const int* __restrict__ ei) {
    int e = blockIdx.x * blockDim.x + threadIdx.x;
    if (e < EE) atomicAdd(&g_deg[ei[e]], 1.0f);
}

// ---------------- launch 2: logdeg ----------------
__global__ void k_logdeg() {
    int n = blockIdx.x * 256 + threadIdx.x;
    if (n < NN) g_logdeg[n] = __logf(g_deg[n] + 1.0f);
}

// ---------------- launch 3 (profiled): encoder via split-fp16 HMMA + fused logits ----------------
// block = 64 nodes x 256 cols; 8 warps: mw = wid&3 (m16), nw = wid>>2 (n128)
extern __shared__ char enc_pool[];
__global__ void __launch_bounds__(256, 2) k_encoder(const float* __restrict__ x,
                                                    const float* __restrict__ b1,
                                                    const float* __restrict__ w2,
                                                    const float* __restrict__ b2) {
    __shared__ float w2s[256][8];
    __shared__ float b1s[256];
    __shared__ float slog[64][8];
    char* pool = enc_pool;
    int tid = threadIdx.x, lane = tid & 31, wid = tid >> 5;
    int mw = wid & 3, nw = wid >> 2;

    for (int i = tid; i < 2048; i += 256) w2s[i >> 3][i & 7] = w2[i];
    if (tid < 256) b1s[tid] = b1[tid];
    for (int i = tid; i < 512; i += 256) ((float*)slog)[i] = 0.0f;   // FIXED: full zero

    int n0 = blockIdx.x * 64;

    auto stageA = [&](int kt, int buf) {
        if (tid < 128) {
            int r = tid >> 1, c = tid & 1;
            int gn = min(n0 + r, NN - 1);
            const float4* xr = (const float4*)x + (size_t)gn * 128 + kt * 4 + c * 2;
            float4 f0 = xr[0], f1 = xr[1];
            float v[8] = {f0.x, f0.y, f0.z, f0.w, f1.x, f1.y, f1.z, f1.w};
            __half hi[8], lo[8];
#pragma unroll
            for (int q = 0; q < 8; q++) {
                __half h = __float2half_rn(v[q]);
                hi[q] = h;
                lo[q] = __float2half_rn(v[q] - __half2float(h));
            }
            int cp = c ^ ((r >> 2) & 1);
            *(uint4*)(pool + (buf * 2 + 0) * 2048 + r * 32 + cp * 16) = *(uint4*)hi;
            *(uint4*)(pool + (buf * 2 + 1) * 2048 + r * 32 + cp * 16) = *(uint4*)lo;
        }
    };
    auto stageB = [&](int kt, int buf) {
#pragma unroll
        for (int q = 0; q < 4; q++) {
            int id = tid + 256 * q;
            int which = id >> 9, rem = id & 511, k = rem >> 5, cu = rem & 31;
            const uint4* src = (const uint4*)(which ? g_w1l : g_w1h);
            uint4 v = src[(size_t)(kt * 16 + k) * 32 + cu];
            int cp = cu ^ (k & 7);
            *(uint4*)(pool + 8192 + (buf * 2 + which) * 8192 + k * 512 + cp * 16) = v;
        }
    };

    stageA(0, 0); stageB(0, 0);
    __syncthreads();

    float acc[16][4];
#pragma unroll
    for (int t = 0; t < 16; t++)
#pragma unroll
        for (int q = 0; q < 4; q++) acc[t][q] = 0.0f;

    uint pbase = smem_u32(pool);
    int q4 = lane >> 3, l8 = lane & 7;
    int arow = mw * 16 + (q4 & 1) * 8 + l8;
    uint aoff = (uint)(arow * 32 + (((q4 >> 1) ^ ((arow >> 2) & 1)) * 16));
    int bk = lane & 15, chi = lane >> 4;
    uint bko = (uint)(bk * 512);

    for (int kt = 0; kt < 32; kt++) {
        int buf = kt & 1;
        if (kt < 31) { stageA(kt + 1, buf ^ 1); stageB(kt + 1, buf ^ 1); }
        uint a1b = pbase + (buf * 2 + 0) * 2048 + aoff;
        uint a2b = pbase + (buf * 2 + 1) * 2048 + aoff;
        uint bhb = pbase + 8192 + (buf * 2 + 0) * 8192 + bko;
        uint blb = pbase + 8192 + (buf * 2 + 1) * 8192 + bko;
        uint A1[4], A2[4];
        ldsm4(A1[0], A1[1], A1[2], A1[3], a1b);
        ldsm4(A2[0], A2[1], A2[2], A2[3], a2b);
#pragma unroll
        for (int t = 0; t < 8; t++) {
            int chunk = nw * 16 + t * 2 + chi;
            uint coff = (uint)((chunk ^ (bk & 7)) * 16);
            uint h0, h1, h2, h3, l0, l1, l2, l3;
            ldsm4t(h0, h1, h2, h3, bhb + coff);
            ldsm4t(l0, l1, l2, l3, blb + coff);
            mma16816(acc[2 * t],     A1, h0, h1);
            mma16816(acc[2 * t + 1], A1, h2, h3);
            mma16816(acc[2 * t],     A1, l0, l1);
            mma16816(acc[2 * t + 1], A1, l2, l3);
            mma16816(acc[2 * t],     A2, h0, h1);
            mma16816(acc[2 * t + 1], A2, h2, h3);
        }
        __syncthreads();
    }

    // epilogue: h16 tile + fp32 logits partials
    int r = lane >> 2, c = lane & 3;
    int row0 = mw * 16 + r;
    float pl0[8], pl1[8];
#pragma unroll
    for (int k = 0; k < 8; k++) { pl0[k] = 0.0f; pl1[k] = 0.0f; }
    __half* h16s = (__half*)pool;
#pragma unroll
    for (int tt = 0; tt < 16; tt++) {
        int j0 = nw * 128 + tt * 8 + 2 * c;
        float hv0 = fmaxf(acc[tt][0] + b1s[j0],     0.0f);
        float hv1 = fmaxf(acc[tt][1] + b1s[j0 + 1], 0.0f);
        float hv2 = fmaxf(acc[tt][2] + b1s[j0],     0.0f);
        float hv3 = fmaxf(acc[tt][3] + b1s[j0 + 1], 0.0f);
        *(__half2*)(h16s + row0 * 264 + j0)       = __floats2half2_rn(hv0, hv1);
        *(__half2*)(h16s + (row0 + 8) * 264 + j0) = __floats2half2_rn(hv2, hv3);
        const float4* w2a = (const float4*)w2s[j0];
        const float4* w2b = (const float4*)w2s[j0 + 1];
        float4 a0 = w2a[0], a1 = w2a[1], b0 = w2b[0], b1v = w2b[1];
        pl0[0] += hv0 * a0.x + hv1 * b0.x;  pl0[1] += hv0 * a0.y + hv1 * b0.y;
        pl0[2] += hv0 * a0.z + hv1 * b0.z;  pl0[3] += hv0 * a0.w + hv1 * b0.w;
        pl0[4] += hv0 * a1.x + hv1 * b1v.x; pl0[5] += hv0 * a1.y + hv1 * b1v.y;
        pl0[6] += hv0 * a1.z + hv1 * b1v.z; pl0[7] += hv0 * a1.w + hv1 * b1v.w;
        pl1[0] += hv2 * a0.x + hv3 * b0.x;  pl1[1] += hv2 * a0.y + hv3 * b0.y;
        pl1[2] += hv2 * a0.z + hv3 * b0.z;  pl1[3] += hv2 * a0.w + hv3 * b0.w;
        pl1[4] += hv2 * a1.x + hv3 * b1v.x; pl1[5] += hv2 * a1.y + hv3 * b1v.y;
        pl1[6] += hv2 * a1.z + hv3 * b1v.z; pl1[7] += hv2 * a1.w + hv3 * b1v.w;
    }
#pragma unroll
    for (int k = 0; k < 8; k++) {
        pl0[k] += __shfl_xor_sync(0xffffffffu, pl0[k], 1);
        pl0[k] += __shfl_xor_sync(0xffffffffu, pl0[k], 2);
        pl1[k] += __shfl_xor_sync(0xffffffffu, pl1[k], 1);
        pl1[k] += __shfl_xor_sync(0xffffffffu, pl1[k], 2);
    }
    if (c == 0) {
#pragma unroll
        for (int k = 0; k < 8; k++) {
            atomicAdd(&slog[row0][k], pl0[k]);
            atomicAdd(&slog[row0 + 8][k], pl1[k]);
        }
    }
    __syncthreads();
#pragma unroll
    for (int i = 0; i < 8; i++) {
        int id = tid + 256 * i;
        int row = id >> 5, cu = id & 31;
        int node = n0 + row;
        if (node < NN) {
            uint4 v = ((uint4*)pool)[row * 33 + cu];
            ((uint4*)g_h16)[(size_t)node * 32 + cu] = v;
        }
    }
    if (tid < 64) {
        int node = n0 + tid;
        if (node < NN) {
            float lg[8], mx = -1e30f;
#pragma unroll
            for (int k = 0; k < 8; k++) { lg[k] = slog[tid][k] + b2[k]; mx = fmaxf(mx, lg[k]); }
            float s = 0.0f;
#pragma unroll
            for (int k = 0; k < 8; k++) s += __expf(lg[k] - mx);
            float lse = mx + __logf(s);
#pragma unroll
            for (int k = 0; k < 8; k++) g_lp[(size_t)node * 8 + k] = lg[k] - lse;
        }
    }
}

// ---------------- launch 4: edge MLP over E2 undirected pairs, HMMA ----------------
__global__ void __launch_bounds__(256, 2) k_edgemlp(const int* __restrict__ ei,
                                                    const float* __restrict__ w1full,
                                                    const float* __restrict__ b1,
                                                    const float* __restrict__ w2,
                                                    const float* __restrict__ b2) {
    __shared__ uint4  stg[2][512];
    __shared__ uint4  wst[2][128];
    __shared__ float4 epi[64];
    __shared__ float  s1s[256], s2s[256];

    int tid  = threadIdx.x;
    int wid  = tid >> 5;
    int lane = tid & 31;
    int e0   = blockIdx.x * 256;

    int nsrc = ei[e0 + tid];
    int ndst = ei[EE + e0 + tid];
    const uint4* pA = (const uint4*)(g_h16 + (size_t)nsrc * 256);
    const uint4* pB = (const uint4*)(g_h16 + (size_t)ndst * 256);
    {
        float a = g_logdeg[nsrc], b = g_logdeg[ndst];
        s1s[tid] = a + b; s2s[tid] = fabsf(a - b);
    }
    if (tid < 64)
        epi[tid] = make_float4(w1full[512 * 64 + tid], w1full[513 * 64 + tid],
                               b1[tid], w2[tid]);
    stg[0][tid]       = pA[0];
    stg[0][256 + tid] = pB[0];
    if (tid < 128) wst[0][tid] = ((const uint4*)g_Wab16)[tid];
    __syncthreads();

    float acc[2][8][4];
#pragma unroll
    for (int mt = 0; mt < 2; mt++)
#pragma unroll
        for (int t = 0; t < 8; t++)
#pragma unroll
            for (int q = 0; q < 4; q++) acc[mt][t][q] = 0.0f;

    const __half* hb0 = (const __half*)stg[0];
    const __half* hb1 = (const __half*)stg[1];
    unsigned wbase0 = smem_u32(wst[0]);
    unsigned wbase1 = smem_u32(wst[1]);
    int klane = lane & 15;
    int chi   = lane >> 4;
    int xorv  = lane & 7;
    int r = lane >> 2, c = lane & 3;
    int eb = wid * 32;

    for (int kt = 0; kt < 32; kt++) {
        int buf = kt & 1;
        if (kt < 31) {
            stg[buf ^ 1][tid]       = pA[kt + 1];
            stg[buf ^ 1][256 + tid] = pB[kt + 1];
            if (tid < 128) wst[buf ^ 1][tid] = ((const uint4*)g_Wab16)[(kt + 1) * 128 + tid];
        }
        const __half* hb = buf ? hb1 : hb0;
        unsigned wbase = (buf ? wbase1 : wbase0) + (unsigned)(klane * 128);

        unsigned afr[2][4];
#pragma unroll
        for (int mt = 0; mt < 2; mt++) {
            int e1 = eb + mt * 16 + r;
            int e2 = e1 + 8;
            __half hs0 = hb[e1 * 8 + c],      hd0 = hb[2048 + e1 * 8 + c];
            __half hs1 = hb[e2 * 8 + c],      hd1 = hb[2048 + e2 * 8 + c];
            __half hs2 = hb[e1 * 8 + c + 4],  hd2 = hb[2048 + e1 * 8 + c + 4];
            __half hs3 = hb[e2 * 8 + c + 4],  hd3 = hb[2048 + e2 * 8 + c + 4];
            __half2 A0 = __halves2half2(__hmul(hs0, hd0), __habs(__hsub(hs0, hd0)));
            __half2 A1 = __halves2half2(__hmul(hs1, hd1), __habs(__hsub(hs1, hd1)));
            __half2 A2 = __halves2half2(__hmul(hs2, hd2), __habs(__hsub(hs2, hd2)));
            __half2 A3 = __halves2half2(__hmul(hs3, hd3), __habs(__hsub(hs3, hd3)));
            afr[mt][0] = *(unsigned*)&A0; afr[mt][1] = *(unsigned*)&A1;
            afr[mt][2] = *(unsigned*)&A2; afr[mt][3] = *(unsigned*)&A3;
        }
#pragma unroll
        for (int t = 0; t < 4; t++) {
            unsigned b0, b1r, b2r, b3;
            unsigned addr = wbase + (unsigned)((((2 * t + chi) ^ xorv) << 4));
            ldsm4t(b0, b1r, b2r, b3, addr);
#pragma unroll
            for (int mt = 0; mt < 2; mt++) {
                mma16816(acc[mt][2 * t],     afr[mt], b0,  b1r);
                mma16816(acc[mt][2 * t + 1], afr[mt], b2r, b3);
            }
        }
        __syncthreads();
    }

    float b2v = b2[0];
#pragma unroll
    for (int mt = 0; mt < 2; mt++) {
        int er  = eb + mt * 16 + r;
        int er8 = er + 8;
        float s1r = s1s[er], s2r = s2s[er];
        float s18 = s1s[er8], s28 = s2s[er8];
        float vr = 0.0f, v8 = 0.0f;
#pragma unroll
        for (int t = 0; t < 8; t++) {
#pragma unroll
            for (int u = 0; u < 2; u++) {
                float4 pp = epi[t * 8 + c * 2 + u];
                float pre  = acc[mt][t][u]     + s1r * pp.x + s2r * pp.y + pp.z;
                float pre8 = acc[mt][t][2 + u] + s18 * pp.x + s28 * pp.y + pp.z;
                vr += fmaxf(pre, 0.0f) * pp.w;
                v8 += fmaxf(pre8, 0.0f) * pp.w;
            }
        }
        vr += __shfl_xor_sync(0xffffffffu, vr, 1);
        vr += __shfl_xor_sync(0xffffffffu, vr, 2);
        v8 += __shfl_xor_sync(0xffffffffu, v8, 1);
        v8 += __shfl_xor_sync(0xffffffffu, v8, 2);
        if (c == 0) {
            if (e0 + er  < E2n) g_wpre[e0 + er]  = 0.8f / (1.0f + __expf(-(vr + b2v)));
            if (e0 + er8 < E2n) g_wpre[e0 + er8] = 0.8f / (1.0f + __expf(-(v8 + b2v)));
        }
    }
}

// ---------------- launch 5: pair init + first A phase ----------------
__global__ void __launch_bounds__(256) k_initA(const int* __restrict__ ei) {
    __shared__ float Rs[64];
    if (threadIdx.x < 64) Rs[threadIdx.x] = g_R[threadIdx.x];
    __syncthreads();
    int p = blockIdx.x * 256 + threadIdx.x;
    if (p >= E2n) return;
    float w = g_wpre[p];
    g_w[p] = w;
    int s = ei[p], d = ei[EE + p];
    float en = rsqrtf(fmaxf(g_deg[s], 1.0f) * fmaxf(g_deg[d], 1.0f)) * 0.6931471805599453f;
    g_enorm[p] = en;
    const float4* ls4 = (const float4*)(g_lp + (size_t)s * 8);
    const float4* ld4 = (const float4*)(g_lp + (size_t)d * 8);
    float4 sA = ls4[0], sB = ls4[1], dA = ld4[0], dB = ld4[1];
    float mf[8] = {sA.x, sA.y, sA.z, sA.w, sB.x, sB.y, sB.z, sB.w};
    float mb[8] = {dA.x, dA.y, dA.z, dA.w, dB.x, dB.y, dB.z, dB.w};
    float sf = 0.0f, sb = 0.0f;
#pragma unroll
    for (int c = 0; c < 8; c++) { mf[c] = __expf(mf[c]); sf += mf[c];
                                  mb[c] = __expf(mb[c]); sb += mb[c]; }
    float isf = 1.0f / sf, isb = 1.0f / sb;
#pragma unroll
    for (int c = 0; c < 8; c++) { mf[c] *= isf; mb[c] *= isb; }
    float4* mf4 = (float4*)(g_m + (size_t)p * 8);
    float4* mb4 = (float4*)(g_m + (size_t)(p + E2n) * 8);
    mf4[0] = make_float4(mf[0], mf[1], mf[2], mf[3]);
    mf4[1] = make_float4(mf[4], mf[5], mf[6], mf[7]);
    mb4[0] = make_float4(mb[0], mb[1], mb[2], mb[3]);
    mb4[1] = make_float4(mb[4], mb[5], mb[6], mb[7]);
    float ff[8] = {0,0,0,0,0,0,0,0}, fb[8] = {0,0,0,0,0,0,0,0};
#pragma unroll
    for (int c = 0; c < 8; c++)
#pragma unroll
        for (int dd = 0; dd < 8; dd++) {
            float kv = exp2f(w * Rs[c * 8 + dd]);
            ff[dd] += mf[c] * kv;
            fb[dd] += mb[c] * kv;
        }
    float lff[8], lfb[8];
#pragma unroll
    for (int i = 0; i < 8; i++) {
        lff[i] = __log2f(fmaxf(ff[i], 1e-12f)) * en;
        lfb[i] = __log2f(fmaxf(fb[i], 1e-12f)) * en;
    }
    float4* of = (float4*)(g_logf[0] + (size_t)p * 8);
    float4* ob = (float4*)(g_logf[0] + (size_t)(p + E2n) * 8);
    of[0] = make_float4(lff[0], lff[1], lff[2], lff[3]);
    of[1] = make_float4(lff[4], lff[5], lff[6], lff[7]);
    ob[0] = make_float4(lfb[0], lfb[1], lfb[2], lfb[3]);
    ob[1] = make_float4(lfb[4], lfb[5], lfb[6], lfb[7]);
    float* spd = &g_sumin[0][(size_t)d * 8];
    float* sps = &g_sumin[0][(size_t)s * 8];
    red_add_v4(spd,     lff[0], lff[1], lff[2], lff[3]);
    red_add_v4(spd + 4, lff[4], lff[5], lff[6], lff[7]);
    red_add_v4(sps,     lfb[0], lfb[1], lfb[2], lfb[3]);
    red_add_v4(sps + 4, lfb[4], lfb[5], lfb[6], lfb[7]);
}

// ---------------- BP step t (pairs): B(t) then A(t+1) ----------------
__global__ void __launch_bounds__(256) k_bp(const int* __restrict__ ei,
                                            const float* __restrict__ mlogit, int t) {
    __shared__ float Rs[64];
    if (threadIdx.x < 64) Rs[threadIdx.x] = g_R[threadIdx.x];
    __syncthreads();
    int p = blockIdx.x * 256 + threadIdx.x;
    if (p >= E2n) return;
    int pr = t & 1;
    float alpha = 1.5f / (1.0f + __expf(-mlogit[0]));
    int s = ei[p], d = ei[EE + p];
    float w = g_w[p], en = g_enorm[p];
    const float4* sis4 = (const float4*)(g_sumin[t] + (size_t)s * 8);
    const float4* sid4 = (const float4*)(g_sumin[t] + (size_t)d * 8);
    const float4* ls4  = (const float4*)(g_lp + (size_t)s * 8);
    const float4* ld4  = (const float4*)(g_lp + (size_t)d * 8);
    const float4* lff4 = (const float4*)(g_logf[pr] + (size_t)p * 8);
    const float4* lfb4 = (const float4*)(g_logf[pr] + (size_t)(p + E2n) * 8);
    float4* mf4 = (float4*)(g_m + (size_t)p * 8);
    float4* mb4 = (float4*)(g_m + (size_t)(p + E2n) * 8);

    float4 sisA = sis4[0], sisB = sis4[1], sidA = sid4[0], sidB = sid4[1];
    float4 lsA = ls4[0], lsB = ls4[1], ldA = ld4[0], ldB = ld4[1];
    float4 lfA = lff4[0], lfB = lff4[1], lbA = lfb4[0], lbB = lfb4[1];
    float sis[8] = {sisA.x, sisA.y, sisA.z, sisA.w, sisB.x, sisB.y, sisB.z, sisB.w};
    float sid[8] = {sidA.x, sidA.y, sidA.z, sidA.w, sidB.x, sidB.y, sidB.z, sidB.w};
    float lps[8] = {lsA.x, lsA.y, lsA.z, lsA.w, lsB.x, lsB.y, lsB.z, lsB.w};
    float lpd[8] = {ldA.x, ldA.y, ldA.z, ldA.w, ldB.x, ldB.y, ldB.z, ldB.w};
    float lfp[8] = {lfA.x, lfA.y, lfA.z, lfA.w, lfB.x, lfB.y, lfB.z, lfB.w};
    float lbp[8] = {lbA.x, lbA.y, lbA.z, lbA.w, lbB.x, lbB.y, lbB.z, lbB.w};

    float tf[8], tb[8], mxf = -1e30f, mxb = -1e30f;
#pragma unroll
    for (int i = 0; i < 8; i++) {
        tf[i] = lps[i] + alpha * (sis[i] - lbp[i]);
        tb[i] = lpd[i] + alpha * (sid[i] - lfp[i]);
        mxf = fmaxf(mxf, tf[i]); mxb = fmaxf(mxb, tb[i]);
    }
    float ssf = 0.0f, ssb = 0.0f;
#pragma unroll
    for (int i = 0; i < 8; i++) {
        tf[i] = __expf(tf[i] - mxf); ssf += tf[i];
        tb[i] = __expf(tb[i] - mxb); ssb += tb[i];
    }
    float ivf = 0.2f / ssf, ivb = 0.2f / ssb;
    float4 mfA = mf4[0], mfB = mf4[1], mbA = mb4[0], mbB = mb4[1];
    float mf[8] = {mfA.x, mfA.y, mfA.z, mfA.w, mfB.x, mfB.y, mfB.z, mfB.w};
    float mb[8] = {mbA.x, mbA.y, mbA.z, mbA.w, mbB.x, mbB.y, mbB.z, mbB.w};
    float s2f = 0.0f, s2b = 0.0f;
#pragma unroll
    for (int i = 0; i < 8; i++) {
        mf[i] = fmaxf(0.8f * mf[i] + tf[i] * ivf, 1e-12f); s2f += mf[i];
        mb[i] = fmaxf(0.8f * mb[i] + tb[i] * ivb, 1e-12f); s2b += mb[i];
    }
    float i2f = 1.0f / s2f, i2b = 1.0f / s2b;
#pragma unroll
    for (int i = 0; i < 8; i++) { mf[i] *= i2f; mb[i] *= i2b; }
    mf4[0] = make_float4(mf[0], mf[1], mf[2], mf[3]);
    mf4[1] = make_float4(mf[4], mf[5], mf[6], mf[7]);
    mb4[0] = make_float4(mb[0], mb[1], mb[2], mb[3]);
    mb4[1] = make_float4(mb[4], mb[5], mb[6], mb[7]);

    float ff[8] = {0,0,0,0,0,0,0,0}, fb[8] = {0,0,0,0,0,0,0,0};
#pragma unroll
    for (int c = 0; c < 8; c++)
#pragma unroll
        for (int dd = 0; dd < 8; dd++) {
            float kv = exp2f(w * Rs[c * 8 + dd]);
            ff[dd] += mf[c] * kv;
            fb[dd] += mb[c] * kv;
        }
    float lff[8], lfb[8];
#pragma unroll
    for (int i = 0; i < 8; i++) {
        lff[i] = __log2f(fmaxf(ff[i], 1e-12f)) * en;
        lfb[i] = __log2f(fmaxf(fb[i], 1e-12f)) * en;
    }
    float4* of = (float4*)(g_logf[pr ^ 1] + (size_t)p * 8);
    float4* ob = (float4*)(g_logf[pr ^ 1] + (size_t)(p + E2n) * 8);
    of[0] = make_float4(lff[0], lff[1], lff[2], lff[3]);
    of[1] = make_float4(lff[4], lff[5], lff[6], lff[7]);
    ob[0] = make_float4(lfb[0], lfb[1], lfb[2], lfb[3]);
    ob[1] = make_float4(lfb[4], lfb[5], lfb[6], lfb[7]);
    float* spd = &g_sumin[t + 1][(size_t)d * 8];
    float* sps = &g_sumin[t + 1][(size_t)s * 8];
    red_add_v4(spd,     lff[0], lff[1], lff[2], lff[3]);
    red_add_v4(spd + 4, lff[4], lff[5], lff[6], lff[7]);
    red_add_v4(sps,     lfb[0], lfb[1], lfb[2], lfb[3]);
    red_add_v4(sps + 4, lfb[4], lfb[5], lfb[6], lfb[7]);
}

// ---------------- final beliefs ----------------
__global__ void k_belief(const float* __restrict__ mlogit, float* __restrict__ out) {
    int n = blockIdx.x * blockDim.x + threadIdx.x;
    if (n >= NN) return;
    float alpha = 1.5f / (1.0f + __expf(-mlogit[0]));
    float t[8], mx = -1e30f;
#pragma unroll
    for (int c = 0; c < 8; c++) {
        t[c] = g_lp[(size_t)n * 8 + c] + alpha * g_sumin[10][(size_t)n * 8 + c];
        mx = fmaxf(mx, t[c]);
    }
    float sum = 0.0f;
#pragma unroll
    for (int c = 0; c < 8; c++) { t[c] = __expf(t[c] - mx); sum += t[c]; }
    float inv = 1.0f / sum;
#pragma unroll
    for (int c = 0; c < 8; c++) out[(size_t)n * 8 + c] = t[c] * inv;
}

// ---------------- launch ----------------
extern "C" void kernel_launch(void* const* d_in, const int* in_sizes, int n_in,
                              void* d_out, int out_size) {
    const float* x       = (const float*)d_in[0];
    const int*   ei      = (const int*)d_in[1];
    const float* enc_w1  = (const float*)d_in[3];
    const float* enc_b1  = (const float*)d_in[4];
    const float* enc_w2  = (const float*)d_in[5];
    const float* enc_b2  = (const float*)d_in[6];
    const float* edge_w1 = (const float*)d_in[7];
    const float* edge_b1 = (const float*)d_in[8];
    const float* edge_w2 = (const float*)d_in[9];
    const float* edge_b2 = (const float*)d_in[10];
    const float* R_raw   = (const float*)d_in[11];
    const float* rsl     = (const float*)d_in[12];
    const float* mlogit  = (const float*)d_in[13];
    float* out = (float*)d_out;

    cudaFuncSetAttribute(k_encoder, cudaFuncAttributeMaxDynamicSharedMemorySize, 40960);

    int PB = (E2n + 255) / 256;   // 1563 pair blocks

    k_prep_all<<<(11 * NN * 8 + 255) / 256, 256>>>(R_raw, rsl, edge_w1, enc_w1); // 0
    k_deg<<<(EE + 255) / 256, 256>>>(ei);                                        // 1
    k_logdeg<<<(NN + 255) / 256, 256>>>();                                       // 2
    k_encoder<<<(NN + 63) / 64, 256, 40960>>>(x, enc_b1, enc_w2, enc_b2);        // 3 <- profiled
    k_edgemlp<<<PB, 256>>>(ei, edge_w1, edge_b1, edge_w2, edge_b2);              // 4
    k_initA<<<PB, 256>>>(ei);                                                    // 5
    for (int t = 0; t < 10; t++)
        k_bp<<<PB, 256>>>(ei, mlogit, t);                                        // 6..15
    k_belief<<<(NN + 255) / 256, 256>>>(mlogit, out);                            // 16
}

// round 9
// speedup vs baseline: 10.5542x; 1.1405x over previous
#include <cuda_runtime.h>
#include <cuda_fp16.h>
#include <math.h>

#define NN   50000
#define E2n  400000
#define EE   800000

typedef unsigned long long ull;
typedef unsigned int uint;

// ---------------- scratch ----------------
__device__ __align__(16) __half g_h16[(size_t)NN * 256];     // 25.6 MB
__device__ __align__(16) float g_lp[(size_t)NN * 8];
__device__ float g_deg[NN];
__device__ float g_logdeg[NN];
__device__ float g_wpre[E2n];
__device__ float g_w[E2n];
__device__ float g_enorm[E2n];                               // rsqrt(..)*ln2
__device__ __align__(16) float g_m[(size_t)EE * 8];
__device__ __align__(16) __half g_logf16[2][(size_t)EE * 8]; // 2 x 12.8 MB
__device__ __align__(32) float g_sumin[11][(size_t)NN * 8];  // pre-zeroed
__device__ __align__(16) float g_R[64];                      // R * log2(e)
__device__ __align__(16) __half g_Wab16[512 * 64];           // edge_w1 interleaved+swizzled
__device__ __align__(16) __half g_w1h[512 * 256];            // enc_w1 hi
__device__ __align__(16) __half g_w1l[512 * 256];            // enc_w1 lo residual

// ---------------- helpers ----------------
__device__ __forceinline__ void red_add_v4(float* p, float a, float b, float c, float d) {
    ull gp = (ull)__cvta_generic_to_global(p);
    asm volatile("red.global.add.v4.f32 [%0], {%1,%2,%3,%4};"
                 :: "l"(gp), "f"(a), "f"(b), "f"(c), "f"(d) : "memory");
}
__device__ __forceinline__ unsigned smem_u32(const void* p) {
    unsigned a;
    asm("{ .reg .u64 t; cvta.to.shared.u64 t, %1; cvt.u32.u64 %0, t; }" : "=r"(a) : "l"(p));
    return a;
}
__device__ __forceinline__ void cpa16(uint saddr, const void* g) {
    asm volatile("cp.async.cg.shared.global [%0], [%1], 16;" :: "r"(saddr), "l"(g));
}
#define CPA_COMMIT() asm volatile("cp.async.commit_group;")
#define CPA_WAIT1()  asm volatile("cp.async.wait_group 1;")
#define CPA_WAIT0()  asm volatile("cp.async.wait_group 0;")
__device__ __forceinline__ void ldsm4(uint& a, uint& b, uint& c, uint& d, uint addr) {
    asm volatile("ldmatrix.sync.aligned.m8n8.x4.shared.b16 {%0,%1,%2,%3}, [%4];"
                 : "=r"(a), "=r"(b), "=r"(c), "=r"(d) : "r"(addr));
}
__device__ __forceinline__ void ldsm4t(uint& a, uint& b, uint& c, uint& d, uint addr) {
    asm volatile("ldmatrix.sync.aligned.m8n8.x4.trans.shared.b16 {%0,%1,%2,%3}, [%4];"
                 : "=r"(a), "=r"(b), "=r"(c), "=r"(d) : "r"(addr));
}
__device__ __forceinline__ void mma16816(float* acc, const uint* a, uint b0, uint b1) {
    asm volatile("mma.sync.aligned.m16n8k16.row.col.f32.f16.f16.f32 "
                 "{%0,%1,%2,%3}, {%4,%5,%6,%7}, {%8,%9}, {%0,%1,%2,%3};"
                 : "+f"(acc[0]), "+f"(acc[1]), "+f"(acc[2]), "+f"(acc[3])
                 : "r"(a[0]), "r"(a[1]), "r"(a[2]), "r"(a[3]), "r"(b0), "r"(b1));
}
__device__ __forceinline__ uint4 pack8h(const float* v) {
    __half2 a = __floats2half2_rn(v[0], v[1]);
    __half2 b = __floats2half2_rn(v[2], v[3]);
    __half2 c = __floats2half2_rn(v[4], v[5]);
    __half2 d = __floats2half2_rn(v[6], v[7]);
    return make_uint4(*(uint*)&a, *(uint*)&b, *(uint*)&c, *(uint*)&d);
}
__device__ __forceinline__ void unpack8h(uint4 u, float* v) {
    float2 a = __half22float2(*(__half2*)&u.x);
    float2 b = __half22float2(*(__half2*)&u.y);
    float2 c = __half22float2(*(__half2*)&u.z);
    float2 d = __half22float2(*(__half2*)&u.w);
    v[0] = a.x; v[1] = a.y; v[2] = b.x; v[3] = b.y;
    v[4] = c.x; v[5] = c.y; v[6] = d.x; v[7] = d.y;
}

// ---------------- launch 0: prep ----------------
__global__ void k_prep_all(const float* __restrict__ R_raw, const float* __restrict__ rsl,
                           const float* __restrict__ ew1, const float* __restrict__ encw1) {
    int i = blockIdx.x * 256 + threadIdx.x;
    if (i < 11 * NN * 8) ((float*)g_sumin)[i] = 0.0f;
    if (i < NN) g_deg[i] = 0.0f;
    if (i < 512 * 64) {
        int k = i >> 6, j = i & 63;
        int c = j >> 3, u = j & 7;
        int pos = (k << 6) + (((c ^ (k & 7)) << 3) + u);
        int hc = k >> 1;
        float v = (k & 1) ? ew1[(256 + hc) * 64 + j] : ew1[hc * 64 + j];
        g_Wab16[pos] = __float2half_rn(v);
    }
    if (i < 512 * 256) {
        float v = encw1[i];
        __half h = __float2half_rn(v);
        g_w1h[i] = h;
        g_w1l[i] = __float2half_rn(v - __half2float(h));
    }
    if (i < 64) {
        int r = i >> 3, c = i & 7;
        float v = 0.5f * (R_raw[r * 8 + c] + R_raw[c * 8 + r]);
        float s = log1pf(expf(rsl[0])) + 1e-6f;
        g_R[i] = s * tanhf(v) * 1.44269504088896f;
    }
}

// ---------------- launch 1: degree ----------------
__global__ void k_deg(const int* __restrict__ ei) {
    int e = blockIdx.x * blockDim.x + threadIdx.x;
    if (e < EE) atomicAdd(&g_deg[ei[e]], 1.0f);
}

// ---------------- launch 2: encoder (split-fp16 HMMA, cp.async weights) + logdeg + logits ----------------
extern __shared__ char enc_pool[];
__global__ void __launch_bounds__(256, 2) k_encoder(const float* __restrict__ x,
                                                    const float* __restrict__ b1,
                                                    const float* __restrict__ w2,
                                                    const float* __restrict__ b2) {
    __shared__ float w2s[256][8];
    __shared__ float b1s[256];
    __shared__ float slog[64][8];
    char* pool = enc_pool;
    uint pbase = smem_u32(pool);
    int tid = threadIdx.x, lane = tid & 31, wid = tid >> 5;
    int mw = wid & 3, nw = wid >> 2;

    if (blockIdx.x < (NN + 255) / 256) {
        int n = blockIdx.x * 256 + tid;
        if (n < NN) g_logdeg[n] = __logf(g_deg[n] + 1.0f);
    }
    for (int i = tid; i < 2048; i += 256) w2s[i >> 3][i & 7] = w2[i];
    if (tid < 256) b1s[tid] = b1[tid];
    for (int i = tid; i < 512; i += 256) ((float*)slog)[i] = 0.0f;

    int n0 = blockIdx.x * 64;

    auto stageA = [&](int kt, int buf) {           // plain stores (has conversion math)
        if (tid < 128) {
            int r = tid >> 1, c = tid & 1;
            int gn = min(n0 + r, NN - 1);
            const float4* xr = (const float4*)x + (size_t)gn * 128 + kt * 4 + c * 2;
            float4 f0 = xr[0], f1 = xr[1];
            float v[8] = {f0.x, f0.y, f0.z, f0.w, f1.x, f1.y, f1.z, f1.w};
            __half hi[8], lo[8];
#pragma unroll
            for (int q = 0; q < 8; q++) {
                __half h = __float2half_rn(v[q]);
                hi[q] = h;
                lo[q] = __float2half_rn(v[q] - __half2float(h));
            }
            int cp = c ^ ((r >> 2) & 1);
            *(uint4*)(pool + (buf * 2 + 0) * 2048 + r * 32 + cp * 16) = *(uint4*)hi;
            *(uint4*)(pool + (buf * 2 + 1) * 2048 + r * 32 + cp * 16) = *(uint4*)lo;
        }
    };
    auto stageB = [&](int kt, int buf) {           // cp.async
#pragma unroll
        for (int q = 0; q < 4; q++) {
            int id = tid + 256 * q;
            int which = id >> 9, rem = id & 511, k = rem >> 5, cu = rem & 31;
            const char* src = (const char*)(which ? g_w1l : g_w1h)
                              + (((size_t)(kt * 16 + k) * 32 + cu) << 4);
            int cp = cu ^ (k & 7);
            cpa16(pbase + 8192 + (buf * 2 + which) * 8192 + k * 512 + cp * 16, src);
        }
    };

    stageA(0, 0); stageB(0, 0); CPA_COMMIT();

    float acc[16][4];
#pragma unroll
    for (int t = 0; t < 16; t++)
#pragma unroll
        for (int q = 0; q < 4; q++) acc[t][q] = 0.0f;

    int q4 = lane >> 3, l8 = lane & 7;
    int arow = mw * 16 + (q4 & 1) * 8 + l8;
    uint aoff = (uint)(arow * 32 + (((q4 >> 1) ^ ((arow >> 2) & 1)) * 16));
    int bk = lane & 15, chi = lane >> 4;
    uint bko = (uint)(bk * 512);

    for (int kt = 0; kt < 32; kt++) {
        int buf = kt & 1;
        if (kt < 31) {
            stageA(kt + 1, buf ^ 1); stageB(kt + 1, buf ^ 1); CPA_COMMIT();
            CPA_WAIT1();
        } else {
            CPA_WAIT0();
        }
        __syncthreads();
        uint a1b = pbase + (buf * 2 + 0) * 2048 + aoff;
        uint a2b = pbase + (buf * 2 + 1) * 2048 + aoff;
        uint bhb = pbase + 8192 + (buf * 2 + 0) * 8192 + bko;
        uint blb = pbase + 8192 + (buf * 2 + 1) * 8192 + bko;
        uint A1[4], A2[4];
        ldsm4(A1[0], A1[1], A1[2], A1[3], a1b);
        ldsm4(A2[0], A2[1], A2[2], A2[3], a2b);
#pragma unroll
        for (int t = 0; t < 8; t++) {
            int chunk = nw * 16 + t * 2 + chi;
            uint coff = (uint)((chunk ^ (bk & 7)) * 16);
            uint h0, h1, h2, h3, l0, l1, l2, l3;
            ldsm4t(h0, h1, h2, h3, bhb + coff);
            ldsm4t(l0, l1, l2, l3, blb + coff);
            mma16816(acc[2 * t],     A1, h0, h1);
            mma16816(acc[2 * t + 1], A1, h2, h3);
            mma16816(acc[2 * t],     A1, l0, l1);
            mma16816(acc[2 * t + 1], A1, l2, l3);
            mma16816(acc[2 * t],     A2, h0, h1);
            mma16816(acc[2 * t + 1], A2, h2, h3);
        }
        __syncthreads();
    }

    // epilogue: h16 tile + fp32 logits partials
    int r = lane >> 2, c = lane & 3;
    int row0 = mw * 16 + r;
    float pl0[8], pl1[8];
#pragma unroll
    for (int k = 0; k < 8; k++) { pl0[k] = 0.0f; pl1[k] = 0.0f; }
    __half* h16s = (__half*)pool;
#pragma unroll
    for (int tt = 0; tt < 16; tt++) {
        int j0 = nw * 128 + tt * 8 + 2 * c;
        float hv0 = fmaxf(acc[tt][0] + b1s[j0],     0.0f);
        float hv1 = fmaxf(acc[tt][1] + b1s[j0 + 1], 0.0f);
        float hv2 = fmaxf(acc[tt][2] + b1s[j0],     0.0f);
        float hv3 = fmaxf(acc[tt][3] + b1s[j0 + 1], 0.0f);
        *(__half2*)(h16s + row0 * 264 + j0)       = __floats2half2_rn(hv0, hv1);
        *(__half2*)(h16s + (row0 + 8) * 264 + j0) = __floats2half2_rn(hv2, hv3);
        const float4* w2a = (const float4*)w2s[j0];
        const float4* w2b = (const float4*)w2s[j0 + 1];
        float4 a0 = w2a[0], a1 = w2a[1], b0 = w2b[0], b1v = w2b[1];
        pl0[0] += hv0 * a0.x + hv1 * b0.x;  pl0[1] += hv0 * a0.y + hv1 * b0.y;
        pl0[2] += hv0 * a0.z + hv1 * b0.z;  pl0[3] += hv0 * a0.w + hv1 * b0.w;
        pl0[4] += hv0 * a1.x + hv1 * b1v.x; pl0[5] += hv0 * a1.y + hv1 * b1v.y;
        pl0[6] += hv0 * a1.z + hv1 * b1v.z; pl0[7] += hv0 * a1.w + hv1 * b1v.w;
        pl1[0] += hv2 * a0.x + hv3 * b0.x;  pl1[1] += hv2 * a0.y + hv3 * b0.y;
        pl1[2] += hv2 * a0.z + hv3 * b0.z;  pl1[3] += hv2 * a0.w + hv3 * b0.w;
        pl1[4] += hv2 * a1.x + hv3 * b1v.x; pl1[5] += hv2 * a1.y + hv3 * b1v.y;
        pl1[6] += hv2 * a1.z + hv3 * b1v.z; pl1[7] += hv2 * a1.w + hv3 * b1v.w;
    }
#pragma unroll
    for (int k = 0; k < 8; k++) {
        pl0[k] += __shfl_xor_sync(0xffffffffu, pl0[k], 1);
        pl0[k] += __shfl_xor_sync(0xffffffffu, pl0[k], 2);
        pl1[k] += __shfl_xor_sync(0xffffffffu, pl1[k], 1);
        pl1[k] += __shfl_xor_sync(0xffffffffu, pl1[k], 2);
    }
    if (c == 0) {
#pragma unroll
        for (int k = 0; k < 8; k++) {
            atomicAdd(&slog[row0][k], pl0[k]);
            atomicAdd(&slog[row0 + 8][k], pl1[k]);
        }
    }
    __syncthreads();
#pragma unroll
    for (int i = 0; i < 8; i++) {
        int id = tid + 256 * i;
        int row = id >> 5, cu = id & 31;
        int node = n0 + row;
        if (node < NN) {
            uint4 v = ((uint4*)pool)[row * 33 + cu];
            ((uint4*)g_h16)[(size_t)node * 32 + cu] = v;
        }
    }
    if (tid < 64) {
        int node = n0 + tid;
        if (node < NN) {
            float lg[8], mx = -1e30f;
#pragma unroll
            for (int k = 0; k < 8; k++) { lg[k] = slog[tid][k] + b2[k]; mx = fmaxf(mx, lg[k]); }
            float s = 0.0f;
#pragma unroll
            for (int k = 0; k < 8; k++) s += __expf(lg[k] - mx);
            float lse = mx + __logf(s);
#pragma unroll
            for (int k = 0; k < 8; k++) g_lp[(size_t)node * 8 + k] = lg[k] - lse;
        }
    }
}

// ---------------- launch 3 (profiled): edge MLP, cp.async gathers ----------------
__global__ void __launch_bounds__(256, 2) k_edgemlp(const int* __restrict__ ei,
                                                    const float* __restrict__ w1full,
                                                    const float* __restrict__ b1,
                                                    const float* __restrict__ w2,
                                                    const float* __restrict__ b2) {
    __shared__ uint4  stg[2][512];     // [buf]: edges 0..255 = hs, 256..511 = hd
    __shared__ uint4  wst[2][128];
    __shared__ float4 epi[64];
    __shared__ float  s1s[256], s2s[256];

    int tid  = threadIdx.x;
    int wid  = tid >> 5;
    int lane = tid & 31;
    int e0   = blockIdx.x * 256;

    uint stgb = smem_u32(stg);
    uint wstb = smem_u32(wst);

    int nsrc = ei[e0 + tid];
    int ndst = ei[EE + e0 + tid];
    const char* pA = (const char*)(g_h16 + (size_t)nsrc * 256);
    const char* pB = (const char*)(g_h16 + (size_t)ndst * 256);
    {
        float a = g_logdeg[nsrc], b = g_logdeg[ndst];
        s1s[tid] = a + b; s2s[tid] = fabsf(a - b);
    }
    if (tid < 64)
        epi[tid] = make_float4(w1full[512 * 64 + tid], w1full[513 * 64 + tid],
                               b1[tid], w2[tid]);
    // preload buf0
    cpa16(stgb + tid * 16,        pA);
    cpa16(stgb + 4096 + tid * 16, pB);
    if (tid < 128) cpa16(wstb + tid * 16, (const char*)g_Wab16 + tid * 16);
    CPA_COMMIT();

    float acc[2][8][4];
#pragma unroll
    for (int mt = 0; mt < 2; mt++)
#pragma unroll
        for (int t = 0; t < 8; t++)
#pragma unroll
            for (int q = 0; q < 4; q++) acc[mt][t][q] = 0.0f;

    int klane = lane & 15;
    int chi   = lane >> 4;
    int xorv  = lane & 7;
    int r = lane >> 2, c = lane & 3;
    int eb = wid * 32;

    for (int kt = 0; kt < 32; kt++) {
        int buf = kt & 1;
        if (kt < 31) {
            uint db = stgb + (buf ^ 1) * 8192;
            cpa16(db + tid * 16,        pA + (kt + 1) * 16);
            cpa16(db + 4096 + tid * 16, pB + (kt + 1) * 16);
            if (tid < 128)
                cpa16(wstb + (buf ^ 1) * 2048 + tid * 16,
                      (const char*)g_Wab16 + (kt + 1) * 2048 + tid * 16);
            CPA_COMMIT();
            CPA_WAIT1();
        } else {
            CPA_WAIT0();
        }
        __syncthreads();
        const __half* hb = (const __half*)stg + buf * 4096;
        unsigned wbase = wstb + buf * 2048 + (unsigned)(klane * 128);

        unsigned afr[2][4];
#pragma unroll
        for (int mt = 0; mt < 2; mt++) {
            int e1 = eb + mt * 16 + r;
            int e2 = e1 + 8;
            __half hs0 = hb[e1 * 8 + c],      hd0 = hb[2048 + e1 * 8 + c];
            __half hs1 = hb[e2 * 8 + c],      hd1 = hb[2048 + e2 * 8 + c];
            __half hs2 = hb[e1 * 8 + c + 4],  hd2 = hb[2048 + e1 * 8 + c + 4];
            __half hs3 = hb[e2 * 8 + c + 4],  hd3 = hb[2048 + e2 * 8 + c + 4];
            __half2 A0 = __halves2half2(__hmul(hs0, hd0), __habs(__hsub(hs0, hd0)));
            __half2 A1 = __halves2half2(__hmul(hs1, hd1), __habs(__hsub(hs1, hd1)));
            __half2 A2 = __halves2half2(__hmul(hs2, hd2), __habs(__hsub(hs2, hd2)));
            __half2 A3 = __halves2half2(__hmul(hs3, hd3), __habs(__hsub(hs3, hd3)));
            afr[mt][0] = *(unsigned*)&A0; afr[mt][1] = *(unsigned*)&A1;
            afr[mt][2] = *(unsigned*)&A2; afr[mt][3] = *(unsigned*)&A3;
        }
#pragma unroll
        for (int t = 0; t < 4; t++) {
            unsigned b0, b1r, b2r, b3;
            unsigned addr = wbase + (unsigned)((((2 * t + chi) ^ xorv) << 4));
            ldsm4t(b0, b1r, b2r, b3, addr);
#pragma unroll
            for (int mt = 0; mt < 2; mt++) {
                mma16816(acc[mt][2 * t],     afr[mt], b0,  b1r);
                mma16816(acc[mt][2 * t + 1], afr[mt], b2r, b3);
            }
        }
        __syncthreads();
    }

    float b2v = b2[0];
#pragma unroll
    for (int mt = 0; mt < 2; mt++) {
        int er  = eb + mt * 16 + r;
        int er8 = er + 8;
        float s1r = s1s[er], s2r = s2s[er];
        float s18 = s1s[er8], s28 = s2s[er8];
        float vr = 0.0f, v8 = 0.0f;
#pragma unroll
        for (int t = 0; t < 8; t++) {
#pragma unroll
            for (int u = 0; u < 2; u++) {
                float4 pp = epi[t * 8 + c * 2 + u];
                float pre  = acc[mt][t][u]     + s1r * pp.x + s2r * pp.y + pp.z;
                float pre8 = acc[mt][t][2 + u] + s18 * pp.x + s28 * pp.y + pp.z;
                vr += fmaxf(pre, 0.0f) * pp.w;
                v8 += fmaxf(pre8, 0.0f) * pp.w;
            }
        }
        vr += __shfl_xor_sync(0xffffffffu, vr, 1);
        vr += __shfl_xor_sync(0xffffffffu, vr, 2);
        v8 += __shfl_xor_sync(0xffffffffu, v8, 1);
        v8 += __shfl_xor_sync(0xffffffffu, v8, 2);
        if (c == 0) {
            if (e0 + er  < E2n) g_wpre[e0 + er]  = 0.8f / (1.0f + __expf(-(vr + b2v)));
            if (e0 + er8 < E2n) g_wpre[e0 + er8] = 0.8f / (1.0f + __expf(-(v8 + b2v)));
        }
    }
}

// ---------------- launch 4: pair init + first A phase ----------------
__global__ void __launch_bounds__(256) k_initA(const int* __restrict__ ei) {
    __shared__ float Rs[64];
    if (threadIdx.x < 64) Rs[threadIdx.x] = g_R[threadIdx.x];
    __syncthreads();
    int p = blockIdx.x * 256 + threadIdx.x;
    if (p >= E2n) return;
    float w = g_wpre[p];
    g_w[p] = w;
    int s = ei[p], d = ei[EE + p];
    float en = rsqrtf(fmaxf(g_deg[s], 1.0f) * fmaxf(g_deg[d], 1.0f)) * 0.6931471805599453f;
    g_enorm[p] = en;
    const float4* ls4 = (const float4*)(g_lp + (size_t)s * 8);
    const float4* ld4 = (const float4*)(g_lp + (size_t)d * 8);
    float4 sA = ls4[0], sB = ls4[1], dA = ld4[0], dB = ld4[1];
    float mf[8] = {sA.x, sA.y, sA.z, sA.w, sB.x, sB.y, sB.z, sB.w};
    float mb[8] = {dA.x, dA.y, dA.z, dA.w, dB.x, dB.y, dB.z, dB.w};
    float sf = 0.0f, sb = 0.0f;
#pragma unroll
    for (int c = 0; c < 8; c++) { mf[c] = __expf(mf[c]); sf += mf[c];
                                  mb[c] = __expf(mb[c]); sb += mb[c]; }
    float isf = 1.0f / sf, isb = 1.0f / sb;
#pragma unroll
    for (int c = 0; c < 8; c++) { mf[c] *= isf; mb[c] *= isb; }
    float4* mf4 = (float4*)(g_m + (size_t)p * 8);
    float4* mb4 = (float4*)(g_m + (size_t)(p + E2n) * 8);
    mf4[0] = make_float4(mf[0], mf[1], mf[2], mf[3]);
    mf4[1] = make_float4(mf[4], mf[5], mf[6], mf[7]);
    mb4[0] = make_float4(mb[0], mb[1], mb[2], mb[3]);
    mb4[1] = make_float4(mb[4], mb[5], mb[6], mb[7]);
    float ff[8] = {0,0,0,0,0,0,0,0}, fb[8] = {0,0,0,0,0,0,0,0};
#pragma unroll
    for (int c = 0; c < 8; c++)
#pragma unroll
        for (int dd = 0; dd < 8; dd++) {
            float kv = exp2f(w * Rs[c * 8 + dd]);
            ff[dd] += mf[c] * kv;
            fb[dd] += mb[c] * kv;
        }
    float lff[8], lfb[8];
#pragma unroll
    for (int i = 0; i < 8; i++) {
        lff[i] = __log2f(fmaxf(ff[i], 1e-12f)) * en;
        lfb[i] = __log2f(fmaxf(fb[i], 1e-12f)) * en;
    }
    ((uint4*)g_logf16[0])[p]       = pack8h(lff);
    ((uint4*)g_logf16[0])[p + E2n] = pack8h(lfb);
    float* spd = &g_sumin[0][(size_t)d * 8];
    float* sps = &g_sumin[0][(size_t)s * 8];
    red_add_v4(spd,     lff[0], lff[1], lff[2], lff[3]);
    red_add_v4(spd + 4, lff[4], lff[5], lff[6], lff[7]);
    red_add_v4(sps,     lfb[0], lfb[1], lfb[2], lfb[3]);
    red_add_v4(sps + 4, lfb[4], lfb[5], lfb[6], lfb[7]);
}

// ---------------- BP step t (pairs): B(t) then A(t+1) ----------------
__global__ void __launch_bounds__(256) k_bp(const int* __restrict__ ei,
                                            const float* __restrict__ mlogit, int t) {
    __shared__ float Rs[64];
    if (threadIdx.x < 64) Rs[threadIdx.x] = g_R[threadIdx.x];
    __syncthreads();
    int p = blockIdx.x * 256 + threadIdx.x;
    if (p >= E2n) return;
    int pr = t & 1;
    float alpha = 1.5f / (1.0f + __expf(-mlogit[0]));
    int s = ei[p], d = ei[EE + p];
    float w = g_w[p], en = g_enorm[p];
    const float4* sis4 = (const float4*)(g_sumin[t] + (size_t)s * 8);
    const float4* sid4 = (const float4*)(g_sumin[t] + (size_t)d * 8);
    const float4* ls4  = (const float4*)(g_lp + (size_t)s * 8);
    const float4* ld4  = (const float4*)(g_lp + (size_t)d * 8);
    uint4 vlf = ((const uint4*)g_logf16[pr])[p];
    uint4 vlb = ((const uint4*)g_logf16[pr])[p + E2n];
    float4* mf4 = (float4*)(g_m + (size_t)p * 8);
    float4* mb4 = (float4*)(g_m + (size_t)(p + E2n) * 8);

    float4 sisA = sis4[0], sisB = sis4[1], sidA = sid4[0], sidB = sid4[1];
    float4 lsA = ls4[0], lsB = ls4[1], ldA = ld4[0], ldB = ld4[1];
    float sis[8] = {sisA.x, sisA.y, sisA.z, sisA.w, sisB.x, sisB.y, sisB.z, sisB.w};
    float sid[8] = {sidA.x, sidA.y, sidA.z, sidA.w, sidB.x, sidB.y, sidB.z, sidB.w};
    float lps[8] = {lsA.x, lsA.y, lsA.z, lsA.w, lsB.x, lsB.y, lsB.z, lsB.w};
    float lpd[8] = {ldA.x, ldA.y, ldA.z, ldA.w, ldB.x, ldB.y, ldB.z, ldB.w};
    float lfp[8], lbp[8];
    unpack8h(vlf, lfp);
    unpack8h(vlb, lbp);

    float tf[8], tb[8], mxf = -1e30f, mxb = -1e30f;
#pragma unroll
    for (int i = 0; i < 8; i++) {
        tf[i] = lps[i] + alpha * (sis[i] - lbp[i]);
        tb[i] = lpd[i] + alpha * (sid[i] - lfp[i]);
        mxf = fmaxf(mxf, tf[i]); mxb = fmaxf(mxb, tb[i]);
    }
    float ssf = 0.0f, ssb = 0.0f;
#pragma unroll
    for (int i = 0; i < 8; i++) {
        tf[i] = __expf(tf[i] - mxf); ssf += tf[i];
        tb[i] = __expf(tb[i] - mxb); ssb += tb[i];
    }
    float ivf = 0.2f / ssf, ivb = 0.2f / ssb;
    float4 mfA = mf4[0], mfB = mf4[1], mbA = mb4[0], mbB = mb4[1];
    float mf[8] = {mfA.x, mfA.y, mfA.z, mfA.w, mfB.x, mfB.y, mfB.z, mfB.w};
    float mb[8] = {mbA.x, mbA.y, mbA.z, mbA.w, mbB.x, mbB.y, mbB.z, mbB.w};
    float s2f = 0.0f, s2b = 0.0f;
#pragma unroll
    for (int i = 0; i < 8; i++) {
        mf[i] = fmaxf(0.8f * mf[i] + tf[i] * ivf, 1e-12f); s2f += mf[i];
        mb[i] = fmaxf(0.8f * mb[i] + tb[i] * ivb, 1e-12f); s2b += mb[i];
    }
    float i2f = 1.0f / s2f, i2b = 1.0f / s2b;
#pragma unroll
    for (int i = 0; i < 8; i++) { mf[i] *= i2f; mb[i] *= i2b; }
    mf4[0] = make_float4(mf[0], mf[1], mf[2], mf[3]);
    mf4[1] = make_float4(mf[4], mf[5], mf[6], mf[7]);
    mb4[0] = make_float4(mb[0], mb[1], mb[2], mb[3]);
    mb4[1] = make_float4(mb[4], mb[5], mb[6], mb[7]);

    float ff[8] = {0,0,0,0,0,0,0,0}, fb[8] = {0,0,0,0,0,0,0,0};
#pragma unroll
    for (int c = 0; c < 8; c++)
#pragma unroll
        for (int dd = 0; dd < 8; dd++) {
            float kv = exp2f(w * Rs[c * 8 + dd]);
            ff[dd] += mf[c] * kv;
            fb[dd] += mb[c] * kv;
        }
    float lff[8], lfb[8];
#pragma unroll
    for (int i = 0; i < 8; i++) {
        lff[i] = __log2f(fmaxf(ff[i], 1e-12f)) * en;
        lfb[i] = __log2f(fmaxf(fb[i], 1e-12f)) * en;
    }
    ((uint4*)g_logf16[pr ^ 1])[p]       = pack8h(lff);
    ((uint4*)g_logf16[pr ^ 1])[p + E2n] = pack8h(lfb);
    float* spd = &g_sumin[t + 1][(size_t)d * 8];
    float* sps = &g_sumin[t + 1][(size_t)s * 8];
    red_add_v4(spd,     lff[0], lff[1], lff[2], lff[3]);
    red_add_v4(spd + 4, lff[4], lff[5], lff[6], lff[7]);
    red_add_v4(sps,     lfb[0], lfb[1], lfb[2], lfb[3]);
    red_add_v4(sps + 4, lfb[4], lfb[5], lfb[6], lfb[7]);
}

// ---------------- final beliefs ----------------
__global__ void k_belief(const float* __restrict__ mlogit, float* __restrict__ out) {
    int n = blockIdx.x * blockDim.x + threadIdx.x;
    if (n >= NN) return;
    float alpha = 1.5f / (1.0f + __expf(-mlogit[0]));
    float t[8], mx = -1e30f;
#pragma unroll
    for (int c = 0; c < 8; c++) {
        t[c] = g_lp[(size_t)n * 8 + c] + alpha * g_sumin[10][(size_t)n * 8 + c];
        mx = fmaxf(mx, t[c]);
    }
    float sum = 0.0f;
#pragma unroll
    for (int c = 0; c < 8; c++) { t[c] = __expf(t[c] - mx); sum += t[c]; }
    float inv = 1.0f / sum;
#pragma unroll
    for (int c = 0; c < 8; c++) out[(size_t)n * 8 + c] = t[c] * inv;
}

// ---------------- launch ----------------
extern "C" void kernel_launch(void* const* d_in, const int* in_sizes, int n_in,
                              void* d_out, int out_size) {
    const float* x       = (const float*)d_in[0];
    const int*   ei      = (const int*)d_in[1];
    const float* enc_w1  = (const float*)d_in[3];
    const float* enc_b1  = (const float*)d_in[4];
    const float* enc_w2  = (const float*)d_in[5];
    const float* enc_b2  = (const float*)d_in[6];
    const float* edge_w1 = (const float*)d_in[7];
    const float* edge_b1 = (const float*)d_in[8];
    const float* edge_w2 = (const float*)d_in[9];
    const float* edge_b2 = (const float*)d_in[10];
    const float* R_raw   = (const float*)d_in[11];
    const float* rsl     = (const float*)d_in[12];
    const float* mlogit  = (const float*)d_in[13];
    float* out = (float*)d_out;

    cudaFuncSetAttribute(k_encoder, cudaFuncAttributeMaxDynamicSharedMemorySize, 40960);

    int PB = (E2n + 255) / 256;

    k_prep_all<<<(11 * NN * 8 + 255) / 256, 256>>>(R_raw, rsl, edge_w1, enc_w1); // 0
    k_deg<<<(EE + 255) / 256, 256>>>(ei);                                        // 1
    k_encoder<<<(NN + 63) / 64, 256, 40960>>>(x, enc_b1, enc_w2, enc_b2);        // 2 (+logdeg)
    k_edgemlp<<<PB, 256>>>(ei, edge_w1, edge_b1, edge_w2, edge_b2);              // 3 <- profiled
    k_initA<<<PB, 256>>>(ei);                                                    // 4
    for (int t = 0; t < 10; t++)
        k_bp<<<PB, 256>>>(ei, mlogit, t);                                        // 5..14
    k_belief<<<(NN + 255) / 256, 256>>>(mlogit, out);                            // 15
}